// round 1
// baseline (speedup 1.0000x reference)
#include <cuda_runtime.h>
#include <math.h>
#include <stddef.h>

#define Bn 512
#define Cc 271
#define Tt 281
#define Hh 128
#define G4 512      // 4H
#define H2 256      // 2H
#define NC 1854
#define MBT (Bn*Tt) // 143872 rows

// ---------------- scratch (static device allocations; no cudaMalloc) ----------------
__device__ float g_Xt[(size_t)MBT * Cc];     // [B,T,C]
__device__ float g_xw0f[(size_t)MBT * G4];   // [B,T,4H]
__device__ float g_xw0b[(size_t)MBT * G4];
__device__ float g_xw1f[(size_t)MBT * G4];
__device__ float g_xw1b[(size_t)MBT * G4];
__device__ float g_h0[(size_t)MBT * H2];     // [B,T,2H]
__device__ float g_h1[(size_t)MBT * H2];
__device__ float g_attWT[H2 * H2];           // transposed attention W
__device__ float g_a[MBT];                   // attention logits
__device__ float g_s[MBT];                   // softmax scores
__device__ float g_ws[Bn * H2];              // weighted context

// ---------------- X [B,C,T] -> Xt [B,T,C] ----------------
__global__ void transpose_x(const float* __restrict__ X, float* __restrict__ Xt) {
    __shared__ float tile[32][33];
    const int b = blockIdx.z;
    const int t0 = blockIdx.x * 32;
    const int c0 = blockIdx.y * 32;
    for (int i = threadIdx.y; i < 32; i += 8) {
        int c = c0 + i, t = t0 + threadIdx.x;
        if (c < Cc && t < Tt) tile[i][threadIdx.x] = X[((size_t)b * Cc + c) * Tt + t];
    }
    __syncthreads();
    for (int i = threadIdx.y; i < 32; i += 8) {
        int t = t0 + i, c = c0 + threadIdx.x;
        if (t < Tt && c < Cc) Xt[((size_t)b * Tt + t) * Cc + c] = tile[threadIdx.x][i];
    }
}

// ---------------- attW [2H,2H] -> attWT [2H,2H] transposed ----------------
__global__ void transpose_att(const float* __restrict__ W, float* __restrict__ WT) {
    int i = blockIdx.x, j = threadIdx.x;
    WT[j * H2 + i] = W[i * H2 + j];
}

// ---------------- generic GEMM: C[m,n] = sum_k A[m,k]*Bw[n,k] + bias1[n] + bias2[n] ----------------
// block tile 128x128, K-step 8, 256 threads, 8x8 register tile, single-stage prefetch.
__launch_bounds__(256)
__global__ void gemm_bias(const float* __restrict__ A, const float* __restrict__ Bw,
                          const float* __restrict__ bias1, const float* __restrict__ bias2,
                          float* __restrict__ C, int M, int N, int K) {
    __shared__ float As[8][132];
    __shared__ float Bs[8][132];
    const int tid = threadIdx.x;
    const int m0 = blockIdx.x * 128, n0 = blockIdx.y * 128;
    const int tx = tid & 15, ty = tid >> 4;
    const int lk = tid & 7, lr = tid >> 3;   // loader coords

    float acc[8][8];
#pragma unroll
    for (int i = 0; i < 8; i++)
#pragma unroll
        for (int j = 0; j < 8; j++) acc[i][j] = 0.f;

    const int nStages = (K + 7) / 8;
    // stage 0 direct to smem
#pragma unroll
    for (int i = 0; i < 4; i++) {
        int r = lr + i * 32;
        int gm = m0 + r, gn = n0 + r, gk = lk;
        As[lk][r] = (gm < M && gk < K) ? A[(size_t)gm * K + gk] : 0.f;
        Bs[lk][r] = (gn < N && gk < K) ? Bw[(size_t)gn * K + gk] : 0.f;
    }
    __syncthreads();

    float ra[4], rb[4];
    for (int s = 1; s <= nStages; s++) {
        const int k0 = s * 8;
        const bool has = (s < nStages);
        if (has) {
#pragma unroll
            for (int i = 0; i < 4; i++) {
                int r = lr + i * 32;
                int gm = m0 + r, gn = n0 + r, gk = k0 + lk;
                ra[i] = (gm < M && gk < K) ? A[(size_t)gm * K + gk] : 0.f;
                rb[i] = (gn < N && gk < K) ? Bw[(size_t)gn * K + gk] : 0.f;
            }
        }
#pragma unroll
        for (int kk = 0; kk < 8; kk++) {
            float4 a0 = *(const float4*)&As[kk][ty * 8];
            float4 a1 = *(const float4*)&As[kk][ty * 8 + 4];
            float4 b0 = *(const float4*)&Bs[kk][tx * 8];
            float4 b1 = *(const float4*)&Bs[kk][tx * 8 + 4];
            float av[8] = {a0.x, a0.y, a0.z, a0.w, a1.x, a1.y, a1.z, a1.w};
            float bv[8] = {b0.x, b0.y, b0.z, b0.w, b1.x, b1.y, b1.z, b1.w};
#pragma unroll
            for (int i = 0; i < 8; i++)
#pragma unroll
                for (int j = 0; j < 8; j++) acc[i][j] += av[i] * bv[j];
        }
        __syncthreads();
        if (has) {
#pragma unroll
            for (int i = 0; i < 4; i++) {
                int r = lr + i * 32;
                As[lk][r] = ra[i];
                Bs[lk][r] = rb[i];
            }
            __syncthreads();
        }
    }

    float bv[8];
#pragma unroll
    for (int j = 0; j < 8; j++) {
        int n = n0 + tx * 8 + j;
        float b = 0.f;
        if (n < N) {
            if (bias1) b += bias1[n];
            if (bias2) b += bias2[n];
        }
        bv[j] = b;
    }
#pragma unroll
    for (int i = 0; i < 8; i++) {
        int m = m0 + ty * 8 + i;
        if (m < M) {
#pragma unroll
            for (int j = 0; j < 8; j++) {
                int n = n0 + tx * 8 + j;
                if (n < N) C[(size_t)m * N + n] = acc[i][j] + bv[j];
            }
        }
    }
}

// ---------------- bidirectional LSTM layer (both dirs in one launch) ----------------
// grid = 128 CTAs: blockIdx>>6 = direction, (blockIdx&63)*8 = batch tile of 8 rows.
// 512 threads; thread g owns gate-row g. Low 64 k of w_hh in smem (transposed),
// high 64 k streamed from global (L1-resident after first step).
#define LSTM_SMEM_FLOATS (64*512 + 8*128 + 8*128 + 8*512)
__launch_bounds__(512)
__global__ void lstm_layer(const float* __restrict__ xwf, const float* __restrict__ xwb,
                           const float* __restrict__ whf, const float* __restrict__ whb,
                           float* __restrict__ hout) {
    extern __shared__ float smf[];
    float* wsT  = smf;                   // [64][512] transposed low-k weights
    float* h_s  = smf + 64 * 512;        // [8][128]
    float* c_s  = h_s + 8 * 128;         // [8][128]
    float* gbuf = c_s + 8 * 128;         // [8][512]

    const int tid = threadIdx.x;
    const int dir = blockIdx.x >> 6;
    const int b0  = (blockIdx.x & 63) * 8;
    const float* W  = dir ? whb : whf;
    const float* xw = dir ? xwb : xwf;

    {   // preload transposed low-k half of w_hh
        const float* wr = W + tid * Hh;
#pragma unroll
        for (int k = 0; k < 64; k++) wsT[k * 512 + tid] = wr[k];
    }
    for (int i = tid; i < 8 * 128; i += 512) { h_s[i] = 0.f; c_s[i] = 0.f; }
    __syncthreads();

    const int g = tid;
    const float4* Whi = (const float4*)(W + g * Hh + 64);   // high-k half, 16 float4s
    const int jj = tid & 127;
    const int btp = (tid >> 7) * 2;

    for (int s = 0; s < Tt; s++) {
        const int t = dir ? (Tt - 1 - s) : s;
        float acc[8];
#pragma unroll
        for (int bt = 0; bt < 8; bt++)
            acc[bt] = xw[((size_t)(b0 + bt) * Tt + t) * G4 + g];

#pragma unroll 2
        for (int kc = 0; kc < 64; kc += 4) {
            float w0 = wsT[(kc + 0) * 512 + g];
            float w1 = wsT[(kc + 1) * 512 + g];
            float w2 = wsT[(kc + 2) * 512 + g];
            float w3 = wsT[(kc + 3) * 512 + g];
#pragma unroll
            for (int bt = 0; bt < 8; bt++) {
                float4 h4 = *(const float4*)(h_s + bt * 128 + kc);
                acc[bt] += w0 * h4.x + w1 * h4.y + w2 * h4.z + w3 * h4.w;
            }
        }
#pragma unroll 2
        for (int q = 0; q < 16; q++) {
            float4 w4 = __ldg(Whi + q);
            const int kc = 64 + q * 4;
#pragma unroll
            for (int bt = 0; bt < 8; bt++) {
                float4 h4 = *(const float4*)(h_s + bt * 128 + kc);
                acc[bt] += w4.x * h4.x + w4.y * h4.y + w4.z * h4.z + w4.w * h4.w;
            }
        }
#pragma unroll
        for (int bt = 0; bt < 8; bt++) gbuf[bt * 512 + g] = acc[bt];
        __syncthreads();

#pragma unroll
        for (int r = 0; r < 2; r++) {
            const int bt = btp + r;
            float gi = gbuf[bt * 512 + jj];
            float gf = gbuf[bt * 512 + 128 + jj];
            float gg = gbuf[bt * 512 + 256 + jj];
            float go = gbuf[bt * 512 + 384 + jj];
            float c  = c_s[bt * 128 + jj];
            float si = 1.f / (1.f + expf(-gi));
            float sf = 1.f / (1.f + expf(-gf));
            float so = 1.f / (1.f + expf(-go));
            c = sf * c + si * tanhf(gg);
            float h = so * tanhf(c);
            c_s[bt * 128 + jj] = c;
            h_s[bt * 128 + jj] = h;
            hout[((size_t)(b0 + bt) * Tt + t) * H2 + dir * Hh + jj] = h;
        }
        __syncthreads();
    }
}

// ---------------- attention scores: a[b,t] = v . tanh(h1[b,t,:] @ attW) ----------------
// block = 8 (b,t) rows, 256 threads; thread j streams row j of attWT (contiguous).
__launch_bounds__(256)
__global__ void att_score(const float* __restrict__ h1, const float* __restrict__ WT,
                          const float* __restrict__ v, float* __restrict__ a) {
    __shared__ float hs[8][256];
    __shared__ float red[8][8];
    const int tid = threadIdx.x;
    const int row0 = blockIdx.x * 8;
#pragma unroll
    for (int r = 0; r < 8; r++) hs[r][tid] = h1[(size_t)(row0 + r) * H2 + tid];
    __syncthreads();

    float acc[8] = {0.f, 0.f, 0.f, 0.f, 0.f, 0.f, 0.f, 0.f};
    const float4* wr = (const float4*)(WT + tid * H2);
#pragma unroll 4
    for (int q = 0; q < 64; q++) {
        float4 w4 = __ldg(wr + q);
        const int i = q * 4;
#pragma unroll
        for (int r = 0; r < 8; r++) {
            float4 h4 = *(const float4*)&hs[r][i];
            acc[r] += w4.x * h4.x + w4.y * h4.y + w4.z * h4.z + w4.w * h4.w;
        }
    }
    const float vj = v[tid];
#pragma unroll
    for (int r = 0; r < 8; r++) {
        float x = tanhf(acc[r]) * vj;
#pragma unroll
        for (int o = 16; o > 0; o >>= 1) x += __shfl_down_sync(0xffffffffu, x, o);
        acc[r] = x;
    }
    const int lane = tid & 31, wp = tid >> 5;
    if (lane == 0) {
#pragma unroll
        for (int r = 0; r < 8; r++) red[r][wp] = acc[r];
    }
    __syncthreads();
    if (tid < 8) {
        float sv = 0.f;
#pragma unroll
        for (int w = 0; w < 8; w++) sv += red[tid][w];
        a[row0 + tid] = sv;
    }
}

// ---------------- softmax over T per batch row ----------------
__global__ void softmax_t(const float* __restrict__ a, float* __restrict__ s) {
    __shared__ float red[256];
    const int b = blockIdx.x, tid = threadIdx.x;
    float v0 = (tid < Tt) ? a[b * Tt + tid] : -1e30f;
    float v1 = (tid + 256 < Tt) ? a[b * Tt + tid + 256] : -1e30f;
    red[tid] = fmaxf(v0, v1);
    __syncthreads();
    for (int o = 128; o > 0; o >>= 1) {
        if (tid < o) red[tid] = fmaxf(red[tid], red[tid + o]);
        __syncthreads();
    }
    const float m = red[0];
    __syncthreads();
    float e0 = (tid < Tt) ? expf(v0 - m) : 0.f;
    float e1 = (tid + 256 < Tt) ? expf(v1 - m) : 0.f;
    red[tid] = e0 + e1;
    __syncthreads();
    for (int o = 128; o > 0; o >>= 1) {
        if (tid < o) red[tid] += red[tid + o];
        __syncthreads();
    }
    const float inv = 1.f / red[0];
    if (tid < Tt) s[b * Tt + tid] = e0 * inv;
    if (tid + 256 < Tt) s[b * Tt + tid + 256] = e1 * inv;
}

// ---------------- weighted[b,h] = sum_t h1[b,t,h] * s[b,t] ----------------
__global__ void weighted_sum(const float* __restrict__ h1, const float* __restrict__ s,
                             float* __restrict__ w) {
    __shared__ float ss[Tt];
    const int b = blockIdx.x, tid = threadIdx.x;
    for (int t = tid; t < Tt; t += 256) ss[t] = s[b * Tt + t];
    __syncthreads();
    float acc = 0.f;
    const float* hb = h1 + (size_t)b * Tt * H2 + tid;
    for (int t = 0; t < Tt; t++) acc += hb[(size_t)t * H2] * ss[t];
    w[b * H2 + tid] = acc;
}

// ---------------- launcher ----------------
extern "C" void kernel_launch(void* const* d_in, const int* in_sizes, int n_in,
                              void* d_out, int out_size) {
    (void)in_sizes; (void)n_in; (void)out_size;
    const float* X      = (const float*)d_in[0];
    const float* w_ih0f = (const float*)d_in[1];
    const float* w_hh0f = (const float*)d_in[2];
    const float* b_ih0f = (const float*)d_in[3];
    const float* b_hh0f = (const float*)d_in[4];
    const float* w_ih0b = (const float*)d_in[5];
    const float* w_hh0b = (const float*)d_in[6];
    const float* b_ih0b = (const float*)d_in[7];
    const float* b_hh0b = (const float*)d_in[8];
    const float* w_ih1f = (const float*)d_in[9];
    const float* w_hh1f = (const float*)d_in[10];
    const float* b_ih1f = (const float*)d_in[11];
    const float* b_hh1f = (const float*)d_in[12];
    const float* w_ih1b = (const float*)d_in[13];
    const float* w_hh1b = (const float*)d_in[14];
    const float* b_ih1b = (const float*)d_in[15];
    const float* b_hh1b = (const float*)d_in[16];
    const float* att_W  = (const float*)d_in[17];
    const float* att_v  = (const float*)d_in[18];
    const float* head_W = (const float*)d_in[19];
    const float* head_b = (const float*)d_in[20];
    float* out = (float*)d_out;

    float *Xt, *xw0f, *xw0b, *xw1f, *xw1b, *h0, *h1, *attWT, *aL, *sL, *ws;
    cudaGetSymbolAddress((void**)&Xt,    g_Xt);
    cudaGetSymbolAddress((void**)&xw0f,  g_xw0f);
    cudaGetSymbolAddress((void**)&xw0b,  g_xw0b);
    cudaGetSymbolAddress((void**)&xw1f,  g_xw1f);
    cudaGetSymbolAddress((void**)&xw1b,  g_xw1b);
    cudaGetSymbolAddress((void**)&h0,    g_h0);
    cudaGetSymbolAddress((void**)&h1,    g_h1);
    cudaGetSymbolAddress((void**)&attWT, g_attWT);
    cudaGetSymbolAddress((void**)&aL,    g_a);
    cudaGetSymbolAddress((void**)&sL,    g_s);
    cudaGetSymbolAddress((void**)&ws,    g_ws);

    const int lstm_smem = LSTM_SMEM_FLOATS * 4;  // 155648 B
    cudaFuncSetAttribute(lstm_layer, cudaFuncAttributeMaxDynamicSharedMemorySize, lstm_smem);

    // 1. transpose X, attW
    transpose_x<<<dim3((Tt + 31) / 32, (Cc + 31) / 32, Bn), dim3(32, 8)>>>(X, Xt);
    transpose_att<<<H2, H2>>>(att_W, attWT);

    // 2. layer-0 input projections (biases folded)
    dim3 gproj(MBT / 128, G4 / 128);
    gemm_bias<<<gproj, 256>>>(Xt, w_ih0f, b_ih0f, b_hh0f, xw0f, MBT, G4, Cc);
    gemm_bias<<<gproj, 256>>>(Xt, w_ih0b, b_ih0b, b_hh0b, xw0b, MBT, G4, Cc);

    // 3. layer-0 recurrence (both dirs)
    lstm_layer<<<128, 512, lstm_smem>>>(xw0f, xw0b, w_hh0f, w_hh0b, h0);

    // 4. layer-1 input projections
    gemm_bias<<<gproj, 256>>>(h0, w_ih1f, b_ih1f, b_hh1f, xw1f, MBT, G4, H2);
    gemm_bias<<<gproj, 256>>>(h0, w_ih1b, b_ih1b, b_hh1b, xw1b, MBT, G4, H2);

    // 5. layer-1 recurrence
    lstm_layer<<<128, 512, lstm_smem>>>(xw1f, xw1b, w_hh1f, w_hh1b, h1);

    // 6. attention + softmax + context
    att_score<<<MBT / 8, 256>>>(h1, attWT, att_v, aL);
    softmax_t<<<Bn, 256>>>(aL, sL);
    weighted_sum<<<Bn, 256>>>(h1, sL, ws);

    // 7. classifier head
    gemm_bias<<<dim3((Bn + 127) / 128, (NC + 127) / 128), 256>>>(
        ws, head_W, head_b, nullptr, out, Bn, NC, H2);
}

// round 2
// speedup vs baseline: 1.3133x; 1.3133x over previous
#include <cuda_runtime.h>
#include <math.h>
#include <stddef.h>
#include <stdint.h>

#define Bn 512
#define Cc 271
#define Tt 281
#define Hh 128
#define G4 512      // 4H
#define H2 256      // 2H
#define NC 1854
#define MBT (Bn*Tt) // 143872 rows

// ---------------- scratch (static device allocations; no cudaMalloc) ----------------
__device__ float g_Xt[(size_t)MBT * Cc];     // [B,T,C]
__device__ float g_xw0f[(size_t)MBT * G4];   // [B,T,4H]
__device__ float g_xw0b[(size_t)MBT * G4];
__device__ float g_xw1f[(size_t)MBT * G4];
__device__ float g_xw1b[(size_t)MBT * G4];
__device__ float g_h0[(size_t)MBT * H2];     // [B,T,2H]
__device__ float g_h1[(size_t)MBT * H2];
__device__ float g_attWT[H2 * H2];           // transposed attention W
__device__ float g_a[MBT];                   // attention logits
__device__ float g_s[MBT];                   // softmax scores
__device__ float g_ws[Bn * H2];              // weighted context

// ---------------- X [B,C,T] -> Xt [B,T,C] ----------------
__global__ void transpose_x(const float* __restrict__ X, float* __restrict__ Xt) {
    __shared__ float tile[32][33];
    const int b = blockIdx.z;
    const int t0 = blockIdx.x * 32;
    const int c0 = blockIdx.y * 32;
    for (int i = threadIdx.y; i < 32; i += 8) {
        int c = c0 + i, t = t0 + threadIdx.x;
        if (c < Cc && t < Tt) tile[i][threadIdx.x] = X[((size_t)b * Cc + c) * Tt + t];
    }
    __syncthreads();
    for (int i = threadIdx.y; i < 32; i += 8) {
        int t = t0 + i, c = c0 + threadIdx.x;
        if (t < Tt && c < Cc) Xt[((size_t)b * Tt + t) * Cc + c] = tile[threadIdx.x][i];
    }
}

// ---------------- attW [2H,2H] -> attWT [2H,2H] transposed ----------------
__global__ void transpose_att(const float* __restrict__ W, float* __restrict__ WT) {
    int i = blockIdx.x, j = threadIdx.x;
    WT[j * H2 + i] = W[i * H2 + j];
}

// ---------------- TF32 tensor-core GEMM ----------------
// C[m,n] = sum_k A[m,k]*Bw[n,k] + bias1[n] + bias2[n]
// CTA tile 128x128, BK=32, 256 threads (8 warps, each 64x32 warp tile).
// mma.sync.m16n8k8 tf32, fp32 accumulate. TF32 rounding applied at smem fill.
__device__ __forceinline__ float to_tf32(float x) {
    uint32_t u;
    asm("cvt.rna.tf32.f32 %0, %1;" : "=r"(u) : "f"(x));
    return __uint_as_float(u);
}

__device__ __forceinline__ void mma_tf32(float* c, uint32_t a0, uint32_t a1, uint32_t a2,
                                         uint32_t a3, uint32_t b0, uint32_t b1) {
    asm volatile(
        "mma.sync.aligned.m16n8k8.row.col.f32.tf32.tf32.f32 "
        "{%0,%1,%2,%3}, {%4,%5,%6,%7}, {%8,%9}, {%0,%1,%2,%3};\n"
        : "+f"(c[0]), "+f"(c[1]), "+f"(c[2]), "+f"(c[3])
        : "r"(a0), "r"(a1), "r"(a2), "r"(a3), "r"(b0), "r"(b1));
}

#define LDA 36
__launch_bounds__(256)
__global__ void gemm_tf32(const float* __restrict__ A, const float* __restrict__ Bw,
                          const float* __restrict__ bias1, const float* __restrict__ bias2,
                          float* __restrict__ C, int M, int N, int K) {
    __shared__ float As[128][LDA];
    __shared__ float Bs[128][LDA];
    __shared__ float bias_s[128];

    const int tid = threadIdx.x;
    const int m0 = blockIdx.x * 128, n0 = blockIdx.y * 128;
    const int wid = tid >> 5, lane = tid & 31;
    const int warpM = (wid >> 2) * 64;   // 0 or 64
    const int warpN = (wid & 3) * 32;    // 0,32,64,96
    const int gid = lane >> 2, tig = lane & 3;

    if (tid < 128) bias_s[tid] = bias1[n0 + tid] + bias2[n0 + tid];

    float c[4][4][4];
#pragma unroll
    for (int mt = 0; mt < 4; mt++)
#pragma unroll
        for (int nt = 0; nt < 4; nt++)
#pragma unroll
            for (int q = 0; q < 4; q++) c[mt][nt][q] = 0.f;

    const int nStages = (K + 31) / 32;
    for (int s = 0; s < nStages; s++) {
        const int k0 = s * 32;
#pragma unroll
        for (int i = 0; i < 16; i++) {
            const int idx = tid + i * 256;
            const int r = idx >> 5, cc = idx & 31;
            const int gk = k0 + cc;
            As[r][cc] = (gk < K) ? to_tf32(A[(size_t)(m0 + r) * K + gk]) : 0.f;
            Bs[r][cc] = (gk < K) ? to_tf32(Bw[(size_t)(n0 + r) * K + gk]) : 0.f;
        }
        __syncthreads();

#pragma unroll
        for (int kt = 0; kt < 4; kt++) {
            const int kk = kt * 8;
            uint32_t af[4][4], bf[4][2];
#pragma unroll
            for (int mt = 0; mt < 4; mt++) {
                const int r = warpM + mt * 16 + gid;
                af[mt][0] = __float_as_uint(As[r][kk + tig]);
                af[mt][1] = __float_as_uint(As[r + 8][kk + tig]);
                af[mt][2] = __float_as_uint(As[r][kk + tig + 4]);
                af[mt][3] = __float_as_uint(As[r + 8][kk + tig + 4]);
            }
#pragma unroll
            for (int nt = 0; nt < 4; nt++) {
                const int r = warpN + nt * 8 + gid;
                bf[nt][0] = __float_as_uint(Bs[r][kk + tig]);
                bf[nt][1] = __float_as_uint(Bs[r][kk + tig + 4]);
            }
#pragma unroll
            for (int mt = 0; mt < 4; mt++)
#pragma unroll
                for (int nt = 0; nt < 4; nt++)
                    mma_tf32(c[mt][nt], af[mt][0], af[mt][1], af[mt][2], af[mt][3],
                             bf[nt][0], bf[nt][1]);
        }
        __syncthreads();
    }

#pragma unroll
    for (int mt = 0; mt < 4; mt++) {
        const int m = m0 + warpM + mt * 16 + gid;
#pragma unroll
        for (int nt = 0; nt < 4; nt++) {
            const int nn = warpN + nt * 8 + tig * 2;
            const float bx = bias_s[nn], by = bias_s[nn + 1];
            float2 v0 = make_float2(c[mt][nt][0] + bx, c[mt][nt][1] + by);
            float2 v1 = make_float2(c[mt][nt][2] + bx, c[mt][nt][3] + by);
            *(float2*)(C + (size_t)m * N + n0 + nn) = v0;
            *(float2*)(C + (size_t)(m + 8) * N + n0 + nn) = v1;
        }
    }
}

// ---------------- fp32 GEMM (kept for classifier head) ----------------
__launch_bounds__(256)
__global__ void gemm_bias(const float* __restrict__ A, const float* __restrict__ Bw,
                          const float* __restrict__ bias1, const float* __restrict__ bias2,
                          float* __restrict__ C, int M, int N, int K) {
    __shared__ float As[8][132];
    __shared__ float Bs[8][132];
    const int tid = threadIdx.x;
    const int m0 = blockIdx.x * 128, n0 = blockIdx.y * 128;
    const int tx = tid & 15, ty = tid >> 4;
    const int lk = tid & 7, lr = tid >> 3;

    float acc[8][8];
#pragma unroll
    for (int i = 0; i < 8; i++)
#pragma unroll
        for (int j = 0; j < 8; j++) acc[i][j] = 0.f;

    const int nStages = (K + 7) / 8;
#pragma unroll
    for (int i = 0; i < 4; i++) {
        int r = lr + i * 32;
        int gm = m0 + r, gn = n0 + r, gk = lk;
        As[lk][r] = (gm < M && gk < K) ? A[(size_t)gm * K + gk] : 0.f;
        Bs[lk][r] = (gn < N && gk < K) ? Bw[(size_t)gn * K + gk] : 0.f;
    }
    __syncthreads();

    float ra[4], rb[4];
    for (int s = 1; s <= nStages; s++) {
        const int k0 = s * 8;
        const bool has = (s < nStages);
        if (has) {
#pragma unroll
            for (int i = 0; i < 4; i++) {
                int r = lr + i * 32;
                int gm = m0 + r, gn = n0 + r, gk = k0 + lk;
                ra[i] = (gm < M && gk < K) ? A[(size_t)gm * K + gk] : 0.f;
                rb[i] = (gn < N && gk < K) ? Bw[(size_t)gn * K + gk] : 0.f;
            }
        }
#pragma unroll
        for (int kk = 0; kk < 8; kk++) {
            float4 a0 = *(const float4*)&As[kk][ty * 8];
            float4 a1 = *(const float4*)&As[kk][ty * 8 + 4];
            float4 b0 = *(const float4*)&Bs[kk][tx * 8];
            float4 b1 = *(const float4*)&Bs[kk][tx * 8 + 4];
            float av[8] = {a0.x, a0.y, a0.z, a0.w, a1.x, a1.y, a1.z, a1.w};
            float bv[8] = {b0.x, b0.y, b0.z, b0.w, b1.x, b1.y, b1.z, b1.w};
#pragma unroll
            for (int i = 0; i < 8; i++)
#pragma unroll
                for (int j = 0; j < 8; j++) acc[i][j] += av[i] * bv[j];
        }
        __syncthreads();
        if (has) {
#pragma unroll
            for (int i = 0; i < 4; i++) {
                int r = lr + i * 32;
                As[lk][r] = ra[i];
                Bs[lk][r] = rb[i];
            }
            __syncthreads();
        }
    }

    float bv[8];
#pragma unroll
    for (int j = 0; j < 8; j++) {
        int n = n0 + tx * 8 + j;
        float b = 0.f;
        if (n < N) {
            if (bias1) b += bias1[n];
            if (bias2) b += bias2[n];
        }
        bv[j] = b;
    }
#pragma unroll
    for (int i = 0; i < 8; i++) {
        int m = m0 + ty * 8 + i;
        if (m < M) {
#pragma unroll
            for (int j = 0; j < 8; j++) {
                int n = n0 + tx * 8 + j;
                if (n < N) C[(size_t)m * N + n] = acc[i][j] + bv[j];
            }
        }
    }
}

// ---------------- bidirectional LSTM layer (both dirs in one launch) ----------------
#define LSTM_SMEM_FLOATS (64*512 + 8*128 + 8*128 + 8*512)
__launch_bounds__(512)
__global__ void lstm_layer(const float* __restrict__ xwf, const float* __restrict__ xwb,
                           const float* __restrict__ whf, const float* __restrict__ whb,
                           float* __restrict__ hout) {
    extern __shared__ float smf[];
    float* wsT  = smf;                   // [64][512] transposed low-k weights
    float* h_s  = smf + 64 * 512;        // [8][128]
    float* c_s  = h_s + 8 * 128;         // [8][128]
    float* gbuf = c_s + 8 * 128;         // [8][512]

    const int tid = threadIdx.x;
    const int dir = blockIdx.x >> 6;
    const int b0  = (blockIdx.x & 63) * 8;
    const float* W  = dir ? whb : whf;
    const float* xw = dir ? xwb : xwf;

    {
        const float* wr = W + tid * Hh;
#pragma unroll
        for (int k = 0; k < 64; k++) wsT[k * 512 + tid] = wr[k];
    }
    for (int i = tid; i < 8 * 128; i += 512) { h_s[i] = 0.f; c_s[i] = 0.f; }
    __syncthreads();

    const int g = tid;
    const float4* Whi = (const float4*)(W + g * Hh + 64);
    const int jj = tid & 127;
    const int btp = (tid >> 7) * 2;

    for (int s = 0; s < Tt; s++) {
        const int t = dir ? (Tt - 1 - s) : s;
        float acc[8];
#pragma unroll
        for (int bt = 0; bt < 8; bt++)
            acc[bt] = xw[((size_t)(b0 + bt) * Tt + t) * G4 + g];

#pragma unroll 2
        for (int kc = 0; kc < 64; kc += 4) {
            float w0 = wsT[(kc + 0) * 512 + g];
            float w1 = wsT[(kc + 1) * 512 + g];
            float w2 = wsT[(kc + 2) * 512 + g];
            float w3 = wsT[(kc + 3) * 512 + g];
#pragma unroll
            for (int bt = 0; bt < 8; bt++) {
                float4 h4 = *(const float4*)(h_s + bt * 128 + kc);
                acc[bt] += w0 * h4.x + w1 * h4.y + w2 * h4.z + w3 * h4.w;
            }
        }
#pragma unroll 2
        for (int q = 0; q < 16; q++) {
            float4 w4 = __ldg(Whi + q);
            const int kc = 64 + q * 4;
#pragma unroll
            for (int bt = 0; bt < 8; bt++) {
                float4 h4 = *(const float4*)(h_s + bt * 128 + kc);
                acc[bt] += w4.x * h4.x + w4.y * h4.y + w4.z * h4.z + w4.w * h4.w;
            }
        }
#pragma unroll
        for (int bt = 0; bt < 8; bt++) gbuf[bt * 512 + g] = acc[bt];
        __syncthreads();

#pragma unroll
        for (int r = 0; r < 2; r++) {
            const int bt = btp + r;
            float gi = gbuf[bt * 512 + jj];
            float gf = gbuf[bt * 512 + 128 + jj];
            float gg = gbuf[bt * 512 + 256 + jj];
            float go = gbuf[bt * 512 + 384 + jj];
            float c  = c_s[bt * 128 + jj];
            float si = 1.f / (1.f + expf(-gi));
            float sf = 1.f / (1.f + expf(-gf));
            float so = 1.f / (1.f + expf(-go));
            c = sf * c + si * tanhf(gg);
            float h = so * tanhf(c);
            c_s[bt * 128 + jj] = c;
            h_s[bt * 128 + jj] = h;
            hout[((size_t)(b0 + bt) * Tt + t) * H2 + dir * Hh + jj] = h;
        }
        __syncthreads();
    }
}

// ---------------- attention scores ----------------
__launch_bounds__(256)
__global__ void att_score(const float* __restrict__ h1, const float* __restrict__ WT,
                          const float* __restrict__ v, float* __restrict__ a) {
    __shared__ float hs[8][256];
    __shared__ float red[8][8];
    const int tid = threadIdx.x;
    const int row0 = blockIdx.x * 8;
#pragma unroll
    for (int r = 0; r < 8; r++) hs[r][tid] = h1[(size_t)(row0 + r) * H2 + tid];
    __syncthreads();

    float acc[8] = {0.f, 0.f, 0.f, 0.f, 0.f, 0.f, 0.f, 0.f};
    const float4* wr = (const float4*)(WT + tid * H2);
#pragma unroll 4
    for (int q = 0; q < 64; q++) {
        float4 w4 = __ldg(wr + q);
        const int i = q * 4;
#pragma unroll
        for (int r = 0; r < 8; r++) {
            float4 h4 = *(const float4*)&hs[r][i];
            acc[r] += w4.x * h4.x + w4.y * h4.y + w4.z * h4.z + w4.w * h4.w;
        }
    }
    const float vj = v[tid];
#pragma unroll
    for (int r = 0; r < 8; r++) {
        float x = tanhf(acc[r]) * vj;
#pragma unroll
        for (int o = 16; o > 0; o >>= 1) x += __shfl_down_sync(0xffffffffu, x, o);
        acc[r] = x;
    }
    const int lane = tid & 31, wp = tid >> 5;
    if (lane == 0) {
#pragma unroll
        for (int r = 0; r < 8; r++) red[r][wp] = acc[r];
    }
    __syncthreads();
    if (tid < 8) {
        float sv = 0.f;
#pragma unroll
        for (int w = 0; w < 8; w++) sv += red[tid][w];
        a[row0 + tid] = sv;
    }
}

// ---------------- softmax over T per batch row ----------------
__global__ void softmax_t(const float* __restrict__ a, float* __restrict__ s) {
    __shared__ float red[256];
    const int b = blockIdx.x, tid = threadIdx.x;
    float v0 = (tid < Tt) ? a[b * Tt + tid] : -1e30f;
    float v1 = (tid + 256 < Tt) ? a[b * Tt + tid + 256] : -1e30f;
    red[tid] = fmaxf(v0, v1);
    __syncthreads();
    for (int o = 128; o > 0; o >>= 1) {
        if (tid < o) red[tid] = fmaxf(red[tid], red[tid + o]);
        __syncthreads();
    }
    const float m = red[0];
    __syncthreads();
    float e0 = (tid < Tt) ? expf(v0 - m) : 0.f;
    float e1 = (tid + 256 < Tt) ? expf(v1 - m) : 0.f;
    red[tid] = e0 + e1;
    __syncthreads();
    for (int o = 128; o > 0; o >>= 1) {
        if (tid < o) red[tid] += red[tid + o];
        __syncthreads();
    }
    const float inv = 1.f / red[0];
    if (tid < Tt) s[b * Tt + tid] = e0 * inv;
    if (tid + 256 < Tt) s[b * Tt + tid + 256] = e1 * inv;
}

// ---------------- weighted[b,h] = sum_t h1[b,t,h] * s[b,t] ----------------
__global__ void weighted_sum(const float* __restrict__ h1, const float* __restrict__ s,
                             float* __restrict__ w) {
    __shared__ float ss[Tt];
    const int b = blockIdx.x, tid = threadIdx.x;
    for (int t = tid; t < Tt; t += 256) ss[t] = s[b * Tt + t];
    __syncthreads();
    float acc = 0.f;
    const float* hb = h1 + (size_t)b * Tt * H2 + tid;
    for (int t = 0; t < Tt; t++) acc += hb[(size_t)t * H2] * ss[t];
    w[b * H2 + tid] = acc;
}

// ---------------- launcher ----------------
extern "C" void kernel_launch(void* const* d_in, const int* in_sizes, int n_in,
                              void* d_out, int out_size) {
    (void)in_sizes; (void)n_in; (void)out_size;
    const float* X      = (const float*)d_in[0];
    const float* w_ih0f = (const float*)d_in[1];
    const float* w_hh0f = (const float*)d_in[2];
    const float* b_ih0f = (const float*)d_in[3];
    const float* b_hh0f = (const float*)d_in[4];
    const float* w_ih0b = (const float*)d_in[5];
    const float* w_hh0b = (const float*)d_in[6];
    const float* b_ih0b = (const float*)d_in[7];
    const float* b_hh0b = (const float*)d_in[8];
    const float* w_ih1f = (const float*)d_in[9];
    const float* w_hh1f = (const float*)d_in[10];
    const float* b_ih1f = (const float*)d_in[11];
    const float* b_hh1f = (const float*)d_in[12];
    const float* w_ih1b = (const float*)d_in[13];
    const float* w_hh1b = (const float*)d_in[14];
    const float* b_ih1b = (const float*)d_in[15];
    const float* b_hh1b = (const float*)d_in[16];
    const float* att_W  = (const float*)d_in[17];
    const float* att_v  = (const float*)d_in[18];
    const float* head_W = (const float*)d_in[19];
    const float* head_b = (const float*)d_in[20];
    float* out = (float*)d_out;

    float *Xt, *xw0f, *xw0b, *xw1f, *xw1b, *h0, *h1, *attWT, *aL, *sL, *ws;
    cudaGetSymbolAddress((void**)&Xt,    g_Xt);
    cudaGetSymbolAddress((void**)&xw0f,  g_xw0f);
    cudaGetSymbolAddress((void**)&xw0b,  g_xw0b);
    cudaGetSymbolAddress((void**)&xw1f,  g_xw1f);
    cudaGetSymbolAddress((void**)&xw1b,  g_xw1b);
    cudaGetSymbolAddress((void**)&h0,    g_h0);
    cudaGetSymbolAddress((void**)&h1,    g_h1);
    cudaGetSymbolAddress((void**)&attWT, g_attWT);
    cudaGetSymbolAddress((void**)&aL,    g_a);
    cudaGetSymbolAddress((void**)&sL,    g_s);
    cudaGetSymbolAddress((void**)&ws,    g_ws);

    const int lstm_smem = LSTM_SMEM_FLOATS * 4;
    cudaFuncSetAttribute(lstm_layer, cudaFuncAttributeMaxDynamicSharedMemorySize, lstm_smem);

    // 1. transposes
    transpose_x<<<dim3((Tt + 31) / 32, (Cc + 31) / 32, Bn), dim3(32, 8)>>>(X, Xt);
    transpose_att<<<H2, H2>>>(att_W, attWT);

    // 2. layer-0 input projections (TF32 tensor cores, biases folded)
    dim3 gproj(MBT / 128, G4 / 128);
    gemm_tf32<<<gproj, 256>>>(Xt, w_ih0f, b_ih0f, b_hh0f, xw0f, MBT, G4, Cc);
    gemm_tf32<<<gproj, 256>>>(Xt, w_ih0b, b_ih0b, b_hh0b, xw0b, MBT, G4, Cc);

    // 3. layer-0 recurrence (both dirs)
    lstm_layer<<<128, 512, lstm_smem>>>(xw0f, xw0b, w_hh0f, w_hh0b, h0);

    // 4. layer-1 input projections
    gemm_tf32<<<gproj, 256>>>(h0, w_ih1f, b_ih1f, b_hh1f, xw1f, MBT, G4, H2);
    gemm_tf32<<<gproj, 256>>>(h0, w_ih1b, b_ih1b, b_hh1b, xw1b, MBT, G4, H2);

    // 5. layer-1 recurrence
    lstm_layer<<<128, 512, lstm_smem>>>(xw1f, xw1b, w_hh1f, w_hh1b, h1);

    // 6. attention + softmax + context
    att_score<<<MBT / 8, 256>>>(h1, attWT, att_v, aL);
    softmax_t<<<Bn, 256>>>(aL, sL);
    weighted_sum<<<Bn, 256>>>(h1, sL, ws);

    // 7. classifier head (fp32)
    gemm_bias<<<dim3((Bn + 127) / 128, (NC + 127) / 128), 256>>>(
        ws, head_W, head_b, nullptr, out, Bn, NC, H2);
}

// round 3
// speedup vs baseline: 2.2547x; 1.7168x over previous
#include <cuda_runtime.h>
#include <math.h>
#include <stddef.h>
#include <stdint.h>

#define Bn 512
#define Cc 271
#define Tt 281
#define Hh 128
#define G4 512      // 4H
#define H2 256      // 2H
#define NC 1854
#define MBT (Bn*Tt) // 143872 rows
#define KP0 288     // padded K for layer-0 (multiple of 32, 16B-aligned rows)

typedef unsigned long long ull;

// ---------------- scratch (static device allocations; no cudaMalloc) ----------------
__device__ float g_Xt[(size_t)MBT * KP0];    // [B,T,KP0] zero-padded
__device__ float g_w0f[G4 * KP0];            // padded layer-0 weights
__device__ float g_w0b[G4 * KP0];
__device__ float g_xw0f[(size_t)MBT * G4];   // [B,T,4H]
__device__ float g_xw0b[(size_t)MBT * G4];
__device__ float g_xw1f[(size_t)MBT * G4];
__device__ float g_xw1b[(size_t)MBT * G4];
__device__ float g_h0[(size_t)MBT * H2];     // [B,T,2H]
__device__ float g_h1[(size_t)MBT * H2];
__device__ float g_attWT[H2 * H2];           // transposed attention W
__device__ float g_a[MBT];                   // attention logits
__device__ float g_s[MBT];                   // softmax scores
__device__ float g_ws[Bn * H2];              // weighted context

// ---------------- X [B,C,T] -> Xt [B,T,KP0] (zero-padded cols) ----------------
__global__ void transpose_x(const float* __restrict__ X, float* __restrict__ Xt) {
    __shared__ float tile[32][33];
    const int b = blockIdx.z;
    const int t0 = blockIdx.x * 32;
    const int c0 = blockIdx.y * 32;
    for (int i = threadIdx.y; i < 32; i += 8) {
        int c = c0 + i, t = t0 + threadIdx.x;
        tile[i][threadIdx.x] = (c < Cc && t < Tt) ? X[((size_t)b * Cc + c) * Tt + t] : 0.f;
    }
    __syncthreads();
    for (int i = threadIdx.y; i < 32; i += 8) {
        int t = t0 + i, c = c0 + threadIdx.x;
        if (t < Tt && c < KP0) Xt[((size_t)b * Tt + t) * KP0 + c] = tile[threadIdx.x][i];
    }
}

// ---------------- pad layer-0 weights [4H,271] -> [4H,288] ----------------
__global__ void pad_w(const float* __restrict__ W, float* __restrict__ Wp) {
    int r = blockIdx.x, c = threadIdx.x;
    Wp[r * KP0 + c] = (c < Cc) ? W[r * Cc + c] : 0.f;
}

// ---------------- attW transpose ----------------
__global__ void transpose_att(const float* __restrict__ W, float* __restrict__ WT) {
    int i = blockIdx.x, j = threadIdx.x;
    WT[j * H2 + i] = W[i * H2 + j];
}

// ---------------- TF32 tensor-core GEMM with cp.async 3-stage pipeline ----------------
// C[m,n] = sum_k A[m,k]*Bw[n,k] + bias1[n] + bias2[n]; K multiple of 32, rows 16B-aligned.
__device__ __forceinline__ void mma_tf32(float* c, uint32_t a0, uint32_t a1, uint32_t a2,
                                         uint32_t a3, uint32_t b0, uint32_t b1) {
    asm volatile(
        "mma.sync.aligned.m16n8k8.row.col.f32.tf32.tf32.f32 "
        "{%0,%1,%2,%3}, {%4,%5,%6,%7}, {%8,%9}, {%0,%1,%2,%3};\n"
        : "+f"(c[0]), "+f"(c[1]), "+f"(c[2]), "+f"(c[3])
        : "r"(a0), "r"(a1), "r"(a2), "r"(a3), "r"(b0), "r"(b1));
}

__device__ __forceinline__ void cpa16(float* dst, const float* src) {
    unsigned s = (unsigned)__cvta_generic_to_shared(dst);
    asm volatile("cp.async.cg.shared.global [%0], [%1], 16;" :: "r"(s), "l"(src));
}

#define LDA 36
#define STG_F (128 * LDA)
__launch_bounds__(256)
__global__ void gemm_tf32(const float* __restrict__ A, const float* __restrict__ Bw,
                          const float* __restrict__ bias1, const float* __restrict__ bias2,
                          float* __restrict__ C, int N, int K) {
    extern __shared__ float sm[];
    float* As = sm;                 // [3][128][36]
    float* Bs = sm + 3 * STG_F;     // [3][128][36]
    float* bias_s = Bs + 3 * STG_F; // [128]

    const int tid = threadIdx.x;
    const int m0 = blockIdx.x * 128, n0 = blockIdx.y * 128;
    const int wid = tid >> 5, lane = tid & 31;
    const int warpM = (wid >> 2) * 64;
    const int warpN = (wid & 3) * 32;
    const int gid = lane >> 2, tig = lane & 3;
    const int lr = tid >> 3, lc = (tid & 7) * 4;  // loader: 4 chunks stride 32 rows

    if (tid < 128) bias_s[tid] = bias1[n0 + tid] + bias2[n0 + tid];

    float c[4][4][4];
#pragma unroll
    for (int mt = 0; mt < 4; mt++)
#pragma unroll
        for (int nt = 0; nt < 4; nt++)
#pragma unroll
            for (int q = 0; q < 4; q++) c[mt][nt][q] = 0.f;

    const int nStages = K >> 5;

#define LOAD_STAGE(slot, k0)                                                   \
    {                                                                          \
        _Pragma("unroll")                                                      \
        for (int i = 0; i < 4; i++) {                                          \
            int r = lr + i * 32;                                               \
            cpa16(&As[(slot) * STG_F + r * LDA + lc],                          \
                  A + (size_t)(m0 + r) * K + (k0) + lc);                       \
            cpa16(&Bs[(slot) * STG_F + r * LDA + lc],                          \
                  Bw + (size_t)(n0 + r) * K + (k0) + lc);                      \
        }                                                                      \
    }

    LOAD_STAGE(0, 0);
    asm volatile("cp.async.commit_group;");
    LOAD_STAGE(1, 32);
    asm volatile("cp.async.commit_group;");

    for (int ks = 0; ks < nStages; ks++) {
        asm volatile("cp.async.wait_group 1;");
        __syncthreads();
        const int nx = ks + 2;
        if (nx < nStages) LOAD_STAGE(nx % 3, nx * 32);
        asm volatile("cp.async.commit_group;");

        const float* Ab = As + (ks % 3) * STG_F;
        const float* Bb = Bs + (ks % 3) * STG_F;
#pragma unroll
        for (int kt = 0; kt < 4; kt++) {
            const int kk = kt * 8;
            uint32_t af[4][4], bf[4][2];
#pragma unroll
            for (int mt = 0; mt < 4; mt++) {
                const int r = warpM + mt * 16 + gid;
                af[mt][0] = __float_as_uint(Ab[r * LDA + kk + tig]);
                af[mt][1] = __float_as_uint(Ab[(r + 8) * LDA + kk + tig]);
                af[mt][2] = __float_as_uint(Ab[r * LDA + kk + tig + 4]);
                af[mt][3] = __float_as_uint(Ab[(r + 8) * LDA + kk + tig + 4]);
            }
#pragma unroll
            for (int nt = 0; nt < 4; nt++) {
                const int r = warpN + nt * 8 + gid;
                bf[nt][0] = __float_as_uint(Bb[r * LDA + kk + tig]);
                bf[nt][1] = __float_as_uint(Bb[r * LDA + kk + tig + 4]);
            }
#pragma unroll
            for (int mt = 0; mt < 4; mt++)
#pragma unroll
                for (int nt = 0; nt < 4; nt++)
                    mma_tf32(c[mt][nt], af[mt][0], af[mt][1], af[mt][2], af[mt][3],
                             bf[nt][0], bf[nt][1]);
        }
        __syncthreads();
    }

#pragma unroll
    for (int mt = 0; mt < 4; mt++) {
        const int m = m0 + warpM + mt * 16 + gid;
#pragma unroll
        for (int nt = 0; nt < 4; nt++) {
            const int nn = warpN + nt * 8 + tig * 2;
            const float bx = bias_s[nn], by = bias_s[nn + 1];
            float2 v0 = make_float2(c[mt][nt][0] + bx, c[mt][nt][1] + by);
            float2 v1 = make_float2(c[mt][nt][2] + bx, c[mt][nt][3] + by);
            *(float2*)(C + (size_t)m * N + n0 + nn) = v0;
            *(float2*)(C + (size_t)(m + 8) * N + n0 + nn) = v1;
        }
    }
}

// ---------------- fp32 GEMM (classifier head) ----------------
__launch_bounds__(256)
__global__ void gemm_bias(const float* __restrict__ A, const float* __restrict__ Bw,
                          const float* __restrict__ bias1,
                          float* __restrict__ C, int M, int N, int K) {
    __shared__ float As[8][132];
    __shared__ float Bs[8][132];
    const int tid = threadIdx.x;
    const int m0 = blockIdx.x * 128, n0 = blockIdx.y * 128;
    const int tx = tid & 15, ty = tid >> 4;
    const int lk = tid & 7, lr = tid >> 3;

    float acc[8][8];
#pragma unroll
    for (int i = 0; i < 8; i++)
#pragma unroll
        for (int j = 0; j < 8; j++) acc[i][j] = 0.f;

    const int nStages = (K + 7) / 8;
#pragma unroll
    for (int i = 0; i < 4; i++) {
        int r = lr + i * 32;
        int gm = m0 + r, gn = n0 + r, gk = lk;
        As[lk][r] = (gm < M && gk < K) ? A[(size_t)gm * K + gk] : 0.f;
        Bs[lk][r] = (gn < N && gk < K) ? Bw[(size_t)gn * K + gk] : 0.f;
    }
    __syncthreads();

    float ra[4], rb[4];
    for (int s = 1; s <= nStages; s++) {
        const int k0 = s * 8;
        const bool has = (s < nStages);
        if (has) {
#pragma unroll
            for (int i = 0; i < 4; i++) {
                int r = lr + i * 32;
                int gm = m0 + r, gn = n0 + r, gk = k0 + lk;
                ra[i] = (gm < M && gk < K) ? A[(size_t)gm * K + gk] : 0.f;
                rb[i] = (gn < N && gk < K) ? Bw[(size_t)gn * K + gk] : 0.f;
            }
        }
#pragma unroll
        for (int kk = 0; kk < 8; kk++) {
            float4 a0 = *(const float4*)&As[kk][ty * 8];
            float4 a1 = *(const float4*)&As[kk][ty * 8 + 4];
            float4 b0 = *(const float4*)&Bs[kk][tx * 8];
            float4 b1 = *(const float4*)&Bs[kk][tx * 8 + 4];
            float av[8] = {a0.x, a0.y, a0.z, a0.w, a1.x, a1.y, a1.z, a1.w};
            float bv[8] = {b0.x, b0.y, b0.z, b0.w, b1.x, b1.y, b1.z, b1.w};
#pragma unroll
            for (int i = 0; i < 8; i++)
#pragma unroll
                for (int j = 0; j < 8; j++) acc[i][j] += av[i] * bv[j];
        }
        __syncthreads();
        if (has) {
#pragma unroll
            for (int i = 0; i < 4; i++) {
                int r = lr + i * 32;
                As[lk][r] = ra[i];
                Bs[lk][r] = rb[i];
            }
            __syncthreads();
        }
    }

#pragma unroll
    for (int i = 0; i < 8; i++) {
        int m = m0 + ty * 8 + i;
        if (m < M) {
#pragma unroll
            for (int j = 0; j < 8; j++) {
                int n = n0 + tx * 8 + j;
                if (n < N) C[(size_t)m * N + n] = acc[i][j] + bias1[n];
            }
        }
    }
}

// ---------------- packed f32x2 helpers ----------------
__device__ __forceinline__ ull pack2(float x, float y) {
    ull r;
    asm("mov.b64 %0, {%1,%2};" : "=l"(r) : "r"(__float_as_uint(x)), "r"(__float_as_uint(y)));
    return r;
}
__device__ __forceinline__ ull bcast2(float x) {
    ull r;
    asm("mov.b64 %0, {%1,%1};" : "=l"(r) : "r"(__float_as_uint(x)));
    return r;
}
__device__ __forceinline__ void fma2(ull& a, ull w, ull h) {
    asm("fma.rn.f32x2 %0, %1, %2, %0;" : "+l"(a) : "l"(w), "l"(h));
}
__device__ __forceinline__ void unpack2(ull a, float& x, float& y) {
    uint32_t lo, hi;
    asm("mov.b64 {%0,%1}, %2;" : "=r"(lo), "=r"(hi) : "l"(a));
    x = __uint_as_float(lo); y = __uint_as_float(hi);
}

__device__ __forceinline__ float sigm_f(float x) {
    return __fdividef(1.f, 1.f + __expf(-x));
}
__device__ __forceinline__ float tanh_f(float x) {
    float a = fabsf(x);
    float e = __expf(2.f * a);
    float t = 1.f - __fdividef(2.f, e + 1.f);
    return copysignf(t, x);
}

// ---------------- bidirectional LSTM layer ----------------
// 128 CTAs (64 batch tiles x 2 dirs), 512 threads; thread g owns gate-row g.
// k=0..95 of w_hh in smem (f4 layout [kq][g]), k=96..127 in registers.
// h stored as batch-pair float2; acc via fma.rn.f32x2.
#define WL_F (24 * 512 * 4)                // 49152 floats = 196608 B
#define LSTM_SMEM_B ((WL_F + 1024 + 1024 + 4096) * 4)  // 221184 B
__launch_bounds__(512)
__global__ void lstm_layer(const float* __restrict__ xwf, const float* __restrict__ xwb,
                           const float* __restrict__ whf, const float* __restrict__ whb,
                           float* __restrict__ hout) {
    extern __shared__ float smf[];
    float4* wl4 = (float4*)smf;                    // [24][512] float4 (k-quads)
    float* h2f  = smf + WL_F;                      // [4][128] float2 = 1024 floats
    float* c_s  = h2f + 1024;                      // [8][128]
    float* gbuf = c_s + 1024;                      // [4][512] float2 = 4096 floats

    const int tid = threadIdx.x;
    const int dir = blockIdx.x >> 6;
    const int b0  = (blockIdx.x & 63) * 8;
    const float* W  = dir ? whb : whf;
    const float* xw = dir ? xwb : xwf;
    const int g = tid;

    // preload smem weights: thread g copies its own row k=0..95 as 24 float4
    {
        const float4* Wr = (const float4*)(W + (size_t)g * Hh);
#pragma unroll
        for (int kq = 0; kq < 24; kq++) wl4[kq * 512 + g] = Wr[kq];
    }
    // high-k weights k=96..127 in registers
    float4 whi[8];
    {
        const float4* Wr = (const float4*)(W + (size_t)g * Hh + 96);
#pragma unroll
        for (int q = 0; q < 8; q++) whi[q] = Wr[q];
    }
    for (int i = tid; i < 1024; i += 512) { h2f[i] = 0.f; c_s[i] = 0.f; c_s[i + 512] = 0.f; }
    __syncthreads();

    const ulonglong2* h2u = (const ulonglong2*)h2f;   // [4][64] : pair p, k-pairs
    ull* gbuf2 = (ull*)gbuf;
    const int p_own = tid >> 7;     // batch pair this thread handles in gate phase
    const int jj = tid & 127;

    const int t0 = dir ? (Tt - 1) : 0;
    const int dt = dir ? -1 : 1;

    float cur[8], nxt[8];
#pragma unroll
    for (int bt = 0; bt < 8; bt++)
        cur[bt] = xw[((size_t)(b0 + bt) * Tt + t0) * G4 + g];

    for (int s = 0; s < Tt; s++) {
        const int t = t0 + s * dt;
        // prefetch next step's xw
        if (s + 1 < Tt) {
            const int t2 = t + dt;
#pragma unroll
            for (int bt = 0; bt < 8; bt++)
                nxt[bt] = xw[((size_t)(b0 + bt) * Tt + t2) * G4 + g];
        }

        ull acc[4];
#pragma unroll
        for (int p = 0; p < 4; p++) acc[p] = pack2(cur[2 * p], cur[2 * p + 1]);

        // low k: 24 quads from smem
#pragma unroll
        for (int kq = 0; kq < 24; kq++) {
            float4 w4 = wl4[kq * 512 + g];
            ull w0 = bcast2(w4.x), w1 = bcast2(w4.y), w2 = bcast2(w4.z), w3 = bcast2(w4.w);
#pragma unroll
            for (int p = 0; p < 4; p++) {
                ulonglong2 hA = h2u[p * 64 + 2 * kq];
                ulonglong2 hB = h2u[p * 64 + 2 * kq + 1];
                fma2(acc[p], w0, hA.x);
                fma2(acc[p], w1, hA.y);
                fma2(acc[p], w2, hB.x);
                fma2(acc[p], w3, hB.y);
            }
        }
        // high k: 8 quads from registers (k = 96..127 -> kq 24..31)
#pragma unroll
        for (int q = 0; q < 8; q++) {
            float4 w4 = whi[q];
            ull w0 = bcast2(w4.x), w1 = bcast2(w4.y), w2 = bcast2(w4.z), w3 = bcast2(w4.w);
            const int kq = 24 + q;
#pragma unroll
            for (int p = 0; p < 4; p++) {
                ulonglong2 hA = h2u[p * 64 + 2 * kq];
                ulonglong2 hB = h2u[p * 64 + 2 * kq + 1];
                fma2(acc[p], w0, hA.x);
                fma2(acc[p], w1, hA.y);
                fma2(acc[p], w2, hB.x);
                fma2(acc[p], w3, hB.y);
            }
        }
#pragma unroll
        for (int p = 0; p < 4; p++) gbuf2[p * 512 + g] = acc[p];
        __syncthreads();

        // gate phase: thread handles (pair p_own, row jj), r = 0,1
#pragma unroll
        for (int r = 0; r < 2; r++) {
            const int base = (p_own * 512 + jj) * 2 + r;
            float gi = gbuf[base];
            float gf = gbuf[base + 256];
            float gg = gbuf[base + 512];
            float go = gbuf[base + 768];
            const int bt = 2 * p_own + r;
            float c = c_s[bt * 128 + jj];
            float si = sigm_f(gi);
            float sf = sigm_f(gf);
            float so = sigm_f(go);
            c = sf * c + si * tanh_f(gg);
            float h = so * tanh_f(c);
            c_s[bt * 128 + jj] = c;
            h2f[(p_own * 128 + jj) * 2 + r] = h;
            hout[((size_t)(b0 + bt) * Tt + t) * H2 + dir * Hh + jj] = h;
        }
        __syncthreads();

#pragma unroll
        for (int bt = 0; bt < 8; bt++) cur[bt] = nxt[bt];
    }
}

// ---------------- attention scores ----------------
__launch_bounds__(256)
__global__ void att_score(const float* __restrict__ h1, const float* __restrict__ WT,
                          const float* __restrict__ v, float* __restrict__ a) {
    __shared__ float hs[8][256];
    __shared__ float red[8][8];
    const int tid = threadIdx.x;
    const int row0 = blockIdx.x * 8;
#pragma unroll
    for (int r = 0; r < 8; r++) hs[r][tid] = h1[(size_t)(row0 + r) * H2 + tid];
    __syncthreads();

    float acc[8] = {0.f, 0.f, 0.f, 0.f, 0.f, 0.f, 0.f, 0.f};
    const float4* wr = (const float4*)(WT + tid * H2);
#pragma unroll 4
    for (int q = 0; q < 64; q++) {
        float4 w4 = __ldg(wr + q);
        const int i = q * 4;
#pragma unroll
        for (int r = 0; r < 8; r++) {
            float4 h4 = *(const float4*)&hs[r][i];
            acc[r] += w4.x * h4.x + w4.y * h4.y + w4.z * h4.z + w4.w * h4.w;
        }
    }
    const float vj = v[tid];
#pragma unroll
    for (int r = 0; r < 8; r++) {
        float x = tanhf(acc[r]) * vj;
#pragma unroll
        for (int o = 16; o > 0; o >>= 1) x += __shfl_down_sync(0xffffffffu, x, o);
        acc[r] = x;
    }
    const int lane = tid & 31, wp = tid >> 5;
    if (lane == 0) {
#pragma unroll
        for (int r = 0; r < 8; r++) red[r][wp] = acc[r];
    }
    __syncthreads();
    if (tid < 8) {
        float sv = 0.f;
#pragma unroll
        for (int w = 0; w < 8; w++) sv += red[tid][w];
        a[row0 + tid] = sv;
    }
}

// ---------------- softmax over T per batch row ----------------
__global__ void softmax_t(const float* __restrict__ a, float* __restrict__ s) {
    __shared__ float red[256];
    const int b = blockIdx.x, tid = threadIdx.x;
    float v0 = (tid < Tt) ? a[b * Tt + tid] : -1e30f;
    float v1 = (tid + 256 < Tt) ? a[b * Tt + tid + 256] : -1e30f;
    red[tid] = fmaxf(v0, v1);
    __syncthreads();
    for (int o = 128; o > 0; o >>= 1) {
        if (tid < o) red[tid] = fmaxf(red[tid], red[tid + o]);
        __syncthreads();
    }
    const float m = red[0];
    __syncthreads();
    float e0 = (tid < Tt) ? expf(v0 - m) : 0.f;
    float e1 = (tid + 256 < Tt) ? expf(v1 - m) : 0.f;
    red[tid] = e0 + e1;
    __syncthreads();
    for (int o = 128; o > 0; o >>= 1) {
        if (tid < o) red[tid] += red[tid + o];
        __syncthreads();
    }
    const float inv = 1.f / red[0];
    if (tid < Tt) s[b * Tt + tid] = e0 * inv;
    if (tid + 256 < Tt) s[b * Tt + tid + 256] = e1 * inv;
}

// ---------------- weighted[b,h] = sum_t h1[b,t,h] * s[b,t] ----------------
__global__ void weighted_sum(const float* __restrict__ h1, const float* __restrict__ s,
                             float* __restrict__ w) {
    __shared__ float ss[Tt];
    const int b = blockIdx.x, tid = threadIdx.x;
    for (int t = tid; t < Tt; t += 256) ss[t] = s[b * Tt + t];
    __syncthreads();
    float acc = 0.f;
    const float* hb = h1 + (size_t)b * Tt * H2 + tid;
    for (int t = 0; t < Tt; t++) acc += hb[(size_t)t * H2] * ss[t];
    w[b * H2 + tid] = acc;
}

// ---------------- launcher ----------------
extern "C" void kernel_launch(void* const* d_in, const int* in_sizes, int n_in,
                              void* d_out, int out_size) {
    (void)in_sizes; (void)n_in; (void)out_size;
    const float* X      = (const float*)d_in[0];
    const float* w_ih0f = (const float*)d_in[1];
    const float* w_hh0f = (const float*)d_in[2];
    const float* b_ih0f = (const float*)d_in[3];
    const float* b_hh0f = (const float*)d_in[4];
    const float* w_ih0b = (const float*)d_in[5];
    const float* w_hh0b = (const float*)d_in[6];
    const float* b_ih0b = (const float*)d_in[7];
    const float* b_hh0b = (const float*)d_in[8];
    const float* w_ih1f = (const float*)d_in[9];
    const float* w_hh1f = (const float*)d_in[10];
    const float* b_ih1f = (const float*)d_in[11];
    const float* b_hh1f = (const float*)d_in[12];
    const float* w_ih1b = (const float*)d_in[13];
    const float* w_hh1b = (const float*)d_in[14];
    const float* b_ih1b = (const float*)d_in[15];
    const float* b_hh1b = (const float*)d_in[16];
    const float* att_W  = (const float*)d_in[17];
    const float* att_v  = (const float*)d_in[18];
    const float* head_W = (const float*)d_in[19];
    const float* head_b = (const float*)d_in[20];
    float* out = (float*)d_out;

    float *Xt, *w0f, *w0b, *xw0f, *xw0b, *xw1f, *xw1b, *h0, *h1, *attWT, *aL, *sL, *ws;
    cudaGetSymbolAddress((void**)&Xt,    g_Xt);
    cudaGetSymbolAddress((void**)&w0f,   g_w0f);
    cudaGetSymbolAddress((void**)&w0b,   g_w0b);
    cudaGetSymbolAddress((void**)&xw0f,  g_xw0f);
    cudaGetSymbolAddress((void**)&xw0b,  g_xw0b);
    cudaGetSymbolAddress((void**)&xw1f,  g_xw1f);
    cudaGetSymbolAddress((void**)&xw1b,  g_xw1b);
    cudaGetSymbolAddress((void**)&h0,    g_h0);
    cudaGetSymbolAddress((void**)&h1,    g_h1);
    cudaGetSymbolAddress((void**)&attWT, g_attWT);
    cudaGetSymbolAddress((void**)&aL,    g_a);
    cudaGetSymbolAddress((void**)&sL,    g_s);
    cudaGetSymbolAddress((void**)&ws,    g_ws);

    const int gemm_smem = (3 * STG_F * 2 + 128) * 4;  // ~111 KB
    cudaFuncSetAttribute(gemm_tf32, cudaFuncAttributeMaxDynamicSharedMemorySize, gemm_smem);
    cudaFuncSetAttribute(lstm_layer, cudaFuncAttributeMaxDynamicSharedMemorySize, LSTM_SMEM_B);

    // 1. layout prep
    transpose_x<<<dim3((Tt + 31) / 32, (KP0 + 31) / 32, Bn), dim3(32, 8)>>>(X, Xt);
    pad_w<<<G4, KP0>>>(w_ih0f, w0f);
    pad_w<<<G4, KP0>>>(w_ih0b, w0b);
    transpose_att<<<H2, H2>>>(att_W, attWT);

    // 2. layer-0 input projections (tf32 mma + cp.async)
    dim3 gproj(MBT / 128, G4 / 128);
    gemm_tf32<<<gproj, 256, gemm_smem>>>(Xt, w0f, b_ih0f, b_hh0f, xw0f, G4, KP0);
    gemm_tf32<<<gproj, 256, gemm_smem>>>(Xt, w0b, b_ih0b, b_hh0b, xw0b, G4, KP0);

    // 3. layer-0 recurrence
    lstm_layer<<<128, 512, LSTM_SMEM_B>>>(xw0f, xw0b, w_hh0f, w_hh0b, h0);

    // 4. layer-1 input projections (K = 256, already aligned)
    gemm_tf32<<<gproj, 256, gemm_smem>>>(h0, w_ih1f, b_ih1f, b_hh1f, xw1f, G4, H2);
    gemm_tf32<<<gproj, 256, gemm_smem>>>(h0, w_ih1b, b_ih1b, b_hh1b, xw1b, G4, H2);

    // 5. layer-1 recurrence
    lstm_layer<<<128, 512, LSTM_SMEM_B>>>(xw1f, xw1b, w_hh1f, w_hh1b, h1);

    // 6. attention + softmax + context
    att_score<<<MBT / 8, 256>>>(h1, attWT, att_v, aL);
    softmax_t<<<Bn, 256>>>(aL, sL);
    weighted_sum<<<Bn, 256>>>(h1, sL, ws);

    // 7. classifier head (fp32)
    gemm_bias<<<dim3((Bn + 127) / 128, (NC + 127) / 128), 256>>>(
        ws, head_W, head_b, out, Bn, NC, H2);
}

// round 4
// speedup vs baseline: 3.6035x; 1.5982x over previous
#include <cuda_runtime.h>
#include <math.h>
#include <stddef.h>
#include <stdint.h>

#define Bn 512
#define Cc 271
#define Tt 281
#define Hh 128
#define G4 512      // 4H
#define H2 256      // 2H
#define NC 1854
#define MBT (Bn*Tt) // 143872 rows
#define KP0 288     // padded K for layer-0

// ---------------- scratch (static device allocations; no cudaMalloc) ----------------
__device__ float g_Xt[(size_t)MBT * KP0];    // [B,T,KP0] zero-padded
__device__ float g_w0f[G4 * KP0];            // padded layer-0 weights
__device__ float g_w0b[G4 * KP0];
__device__ float g_xw0f[(size_t)MBT * G4];   // [B,T,4H]
__device__ float g_xw0b[(size_t)MBT * G4];
__device__ float g_xw1f[(size_t)MBT * G4];
__device__ float g_xw1b[(size_t)MBT * G4];
__device__ float g_h0[(size_t)MBT * H2];     // [B,T,2H]
__device__ float g_h1[(size_t)MBT * H2];
__device__ float g_attWT[H2 * H2];           // transposed attention W
__device__ float g_a[MBT];                   // attention logits
__device__ float g_s[MBT];                   // softmax scores
__device__ float g_ws[Bn * H2];              // weighted context

// ---------------- X [B,C,T] -> Xt [B,T,KP0] ----------------
__global__ void transpose_x(const float* __restrict__ X, float* __restrict__ Xt) {
    __shared__ float tile[32][33];
    const int b = blockIdx.z;
    const int t0 = blockIdx.x * 32;
    const int c0 = blockIdx.y * 32;
    for (int i = threadIdx.y; i < 32; i += 8) {
        int c = c0 + i, t = t0 + threadIdx.x;
        tile[i][threadIdx.x] = (c < Cc && t < Tt) ? X[((size_t)b * Cc + c) * Tt + t] : 0.f;
    }
    __syncthreads();
    for (int i = threadIdx.y; i < 32; i += 8) {
        int t = t0 + i, c = c0 + threadIdx.x;
        if (t < Tt && c < KP0) Xt[((size_t)b * Tt + t) * KP0 + c] = tile[threadIdx.x][i];
    }
}

__global__ void pad_w(const float* __restrict__ W, float* __restrict__ Wp) {
    int r = blockIdx.x, c = threadIdx.x;
    Wp[r * KP0 + c] = (c < Cc) ? W[r * Cc + c] : 0.f;
}

__global__ void transpose_att(const float* __restrict__ W, float* __restrict__ WT) {
    int i = blockIdx.x, j = threadIdx.x;
    WT[j * H2 + i] = W[i * H2 + j];
}

// ---------------- tf32 helpers ----------------
__device__ __forceinline__ uint32_t tf32u(float x) {
    uint32_t u;
    asm("cvt.rna.tf32.f32 %0, %1;" : "=r"(u) : "f"(x));
    return u;
}

__device__ __forceinline__ void mma_tf32(float* c, uint32_t a0, uint32_t a1, uint32_t a2,
                                         uint32_t a3, uint32_t b0, uint32_t b1) {
    asm volatile(
        "mma.sync.aligned.m16n8k8.row.col.f32.tf32.tf32.f32 "
        "{%0,%1,%2,%3}, {%4,%5,%6,%7}, {%8,%9}, {%0,%1,%2,%3};\n"
        : "+f"(c[0]), "+f"(c[1]), "+f"(c[2]), "+f"(c[3])
        : "r"(a0), "r"(a1), "r"(a2), "r"(a3), "r"(b0), "r"(b1));
}

__device__ __forceinline__ void cpa16(float* dst, const float* src) {
    unsigned s = (unsigned)__cvta_generic_to_shared(dst);
    asm volatile("cp.async.cg.shared.global [%0], [%1], 16;" :: "r"(s), "l"(src));
}

// ---------------- TF32 GEMM with cp.async 3-stage pipeline ----------------
#define LDA 36
#define STG_F (128 * LDA)
__launch_bounds__(256)
__global__ void gemm_tf32(const float* __restrict__ A, const float* __restrict__ Bw,
                          const float* __restrict__ bias1, const float* __restrict__ bias2,
                          float* __restrict__ C, int N, int K) {
    extern __shared__ float sm[];
    float* As = sm;
    float* Bs = sm + 3 * STG_F;
    float* bias_s = Bs + 3 * STG_F;

    const int tid = threadIdx.x;
    const int m0 = blockIdx.x * 128, n0 = blockIdx.y * 128;
    const int wid = tid >> 5, lane = tid & 31;
    const int warpM = (wid >> 2) * 64;
    const int warpN = (wid & 3) * 32;
    const int gid = lane >> 2, tig = lane & 3;
    const int lr = tid >> 3, lc = (tid & 7) * 4;

    if (tid < 128) bias_s[tid] = bias1[n0 + tid] + bias2[n0 + tid];

    float c[4][4][4];
#pragma unroll
    for (int mt = 0; mt < 4; mt++)
#pragma unroll
        for (int nt = 0; nt < 4; nt++)
#pragma unroll
            for (int q = 0; q < 4; q++) c[mt][nt][q] = 0.f;

    const int nStages = K >> 5;

#define LOAD_STAGE(slot, k0)                                                   \
    {                                                                          \
        _Pragma("unroll")                                                      \
        for (int i = 0; i < 4; i++) {                                          \
            int r = lr + i * 32;                                               \
            cpa16(&As[(slot) * STG_F + r * LDA + lc],                          \
                  A + (size_t)(m0 + r) * K + (k0) + lc);                       \
            cpa16(&Bs[(slot) * STG_F + r * LDA + lc],                          \
                  Bw + (size_t)(n0 + r) * K + (k0) + lc);                      \
        }                                                                      \
    }

    LOAD_STAGE(0, 0);
    asm volatile("cp.async.commit_group;");
    LOAD_STAGE(1, 32);
    asm volatile("cp.async.commit_group;");

    for (int ks = 0; ks < nStages; ks++) {
        asm volatile("cp.async.wait_group 1;");
        __syncthreads();
        const int nx = ks + 2;
        if (nx < nStages) LOAD_STAGE(nx % 3, nx * 32);
        asm volatile("cp.async.commit_group;");

        const float* Ab = As + (ks % 3) * STG_F;
        const float* Bb = Bs + (ks % 3) * STG_F;
#pragma unroll
        for (int kt = 0; kt < 4; kt++) {
            const int kk = kt * 8;
            uint32_t af[4][4], bf[4][2];
#pragma unroll
            for (int mt = 0; mt < 4; mt++) {
                const int r = warpM + mt * 16 + gid;
                af[mt][0] = __float_as_uint(Ab[r * LDA + kk + tig]);
                af[mt][1] = __float_as_uint(Ab[(r + 8) * LDA + kk + tig]);
                af[mt][2] = __float_as_uint(Ab[r * LDA + kk + tig + 4]);
                af[mt][3] = __float_as_uint(Ab[(r + 8) * LDA + kk + tig + 4]);
            }
#pragma unroll
            for (int nt = 0; nt < 4; nt++) {
                const int r = warpN + nt * 8 + gid;
                bf[nt][0] = __float_as_uint(Bb[r * LDA + kk + tig]);
                bf[nt][1] = __float_as_uint(Bb[r * LDA + kk + tig + 4]);
            }
#pragma unroll
            for (int mt = 0; mt < 4; mt++)
#pragma unroll
                for (int nt = 0; nt < 4; nt++)
                    mma_tf32(c[mt][nt], af[mt][0], af[mt][1], af[mt][2], af[mt][3],
                             bf[nt][0], bf[nt][1]);
        }
        __syncthreads();
    }

#pragma unroll
    for (int mt = 0; mt < 4; mt++) {
        const int m = m0 + warpM + mt * 16 + gid;
#pragma unroll
        for (int nt = 0; nt < 4; nt++) {
            const int nn = warpN + nt * 8 + tig * 2;
            const float bx = bias_s[nn], by = bias_s[nn + 1];
            float2 v0 = make_float2(c[mt][nt][0] + bx, c[mt][nt][1] + by);
            float2 v1 = make_float2(c[mt][nt][2] + bx, c[mt][nt][3] + by);
            *(float2*)(C + (size_t)m * N + n0 + nn) = v0;
            *(float2*)(C + (size_t)(m + 8) * N + n0 + nn) = v1;
        }
    }
}

// ---------------- fp32 GEMM (classifier head) ----------------
__launch_bounds__(256)
__global__ void gemm_bias(const float* __restrict__ A, const float* __restrict__ Bw,
                          const float* __restrict__ bias1,
                          float* __restrict__ C, int M, int N, int K) {
    __shared__ float As[8][132];
    __shared__ float Bs[8][132];
    const int tid = threadIdx.x;
    const int m0 = blockIdx.x * 128, n0 = blockIdx.y * 128;
    const int tx = tid & 15, ty = tid >> 4;
    const int lk = tid & 7, lr = tid >> 3;

    float acc[8][8];
#pragma unroll
    for (int i = 0; i < 8; i++)
#pragma unroll
        for (int j = 0; j < 8; j++) acc[i][j] = 0.f;

    const int nStages = (K + 7) / 8;
#pragma unroll
    for (int i = 0; i < 4; i++) {
        int r = lr + i * 32;
        int gm = m0 + r, gn = n0 + r, gk = lk;
        As[lk][r] = (gm < M && gk < K) ? A[(size_t)gm * K + gk] : 0.f;
        Bs[lk][r] = (gn < N && gk < K) ? Bw[(size_t)gn * K + gk] : 0.f;
    }
    __syncthreads();

    float ra[4], rb[4];
    for (int s = 1; s <= nStages; s++) {
        const int k0 = s * 8;
        const bool has = (s < nStages);
        if (has) {
#pragma unroll
            for (int i = 0; i < 4; i++) {
                int r = lr + i * 32;
                int gm = m0 + r, gn = n0 + r, gk = k0 + lk;
                ra[i] = (gm < M && gk < K) ? A[(size_t)gm * K + gk] : 0.f;
                rb[i] = (gn < N && gk < K) ? Bw[(size_t)gn * K + gk] : 0.f;
            }
        }
#pragma unroll
        for (int kk = 0; kk < 8; kk++) {
            float4 a0 = *(const float4*)&As[kk][ty * 8];
            float4 a1 = *(const float4*)&As[kk][ty * 8 + 4];
            float4 b0 = *(const float4*)&Bs[kk][tx * 8];
            float4 b1 = *(const float4*)&Bs[kk][tx * 8 + 4];
            float av[8] = {a0.x, a0.y, a0.z, a0.w, a1.x, a1.y, a1.z, a1.w};
            float bv[8] = {b0.x, b0.y, b0.z, b0.w, b1.x, b1.y, b1.z, b1.w};
#pragma unroll
            for (int i = 0; i < 8; i++)
#pragma unroll
                for (int j = 0; j < 8; j++) acc[i][j] += av[i] * bv[j];
        }
        __syncthreads();
        if (has) {
#pragma unroll
            for (int i = 0; i < 4; i++) {
                int r = lr + i * 32;
                As[lk][r] = ra[i];
                Bs[lk][r] = rb[i];
            }
            __syncthreads();
        }
    }

#pragma unroll
    for (int i = 0; i < 8; i++) {
        int m = m0 + ty * 8 + i;
        if (m < M) {
#pragma unroll
            for (int j = 0; j < 8; j++) {
                int n = n0 + tx * 8 + j;
                if (n < N) C[(size_t)m * N + n] = acc[i][j] + bias1[n];
            }
        }
    }
}

// ---------------- activations ----------------
__device__ __forceinline__ float sigm_f(float x) {
    return __fdividef(1.f, 1.f + __expf(-x));
}
__device__ __forceinline__ float tanh_f(float x) {
    float a = fabsf(x);
    float e = __expf(2.f * a);
    float t = 1.f - __fdividef(2.f, e + 1.f);
    return copysignf(t, x);
}

// ---------------- bidirectional LSTM layer: tensor-core recurrence ----------------
// 128 CTAs: (dir, batch-tile of 8). Per step: gates_rec = h @ W_hh^T via
// mma.m16n8k8 tf32, M=16 (rows 8..15 zero-padded), N=512, K=128.
// W fragments: k<32 in registers, k>=32 pre-packed in smem (conflict-free).
#define WF_F (16 * 12 * 4 * 32 * 2)          // 49152 floats (smem W fragments)
#define HS_F (16 * 132)                      // 2112
#define GB_F (8 * 520)                       // 4160
#define LSTM2_SMEM_B ((WF_F + HS_F + GB_F) * 4)   // 221696 B
__launch_bounds__(512)
__global__ void lstm_layer_mma(const float* __restrict__ xwf, const float* __restrict__ xwb,
                               const float* __restrict__ whf, const float* __restrict__ whb,
                               float* __restrict__ hout) {
    extern __shared__ float smf[];
    float* Wfrag = smf;               // [wid][ks-4][nt][lane][2]
    float* h_s   = smf + WF_F;        // [16][132], rows 8..15 stay zero
    float* gbuf  = h_s + HS_F;        // [8][520]

    const int tid = threadIdx.x;
    const int wid = tid >> 5, lane = tid & 31;
    const int gid = lane >> 2, tig = lane & 3;
    const int dir = blockIdx.x >> 6;
    const int b0  = (blockIdx.x & 63) * 8;
    const float* W  = dir ? whb : whf;
    const float* xw = dir ? xwb : xwf;

    // ---- prepack W_hh fragments (once) ----
    uint32_t breg[4][4][2];
#pragma unroll
    for (int ks = 0; ks < 4; ks++)
#pragma unroll
        for (int nt = 0; nt < 4; nt++) {
            const int n = wid * 32 + nt * 8 + gid;
            const int k = ks * 8 + tig;
            breg[ks][nt][0] = tf32u(W[n * Hh + k]);
            breg[ks][nt][1] = tf32u(W[n * Hh + k + 4]);
        }
    for (int ks = 4; ks < 16; ks++)
#pragma unroll
        for (int nt = 0; nt < 4; nt++) {
            const int n = wid * 32 + nt * 8 + gid;
            const int k = ks * 8 + tig;
            float2 f2;
            f2.x = __uint_as_float(tf32u(W[n * Hh + k]));
            f2.y = __uint_as_float(tf32u(W[n * Hh + k + 4]));
            *(float2*)&Wfrag[wid * 3072 + ((ks - 4) * 4 + nt) * 64 + lane * 2] = f2;
        }
    for (int i = tid; i < HS_F; i += 512) h_s[i] = 0.f;

    // gate-phase identity: thread -> (batch row bt, units jj and jj+64)
    const int bt = tid >> 6;
    const int jj = tid & 63;
    float c0 = 0.f, c1 = 0.f;

    const int t0 = dir ? (Tt - 1) : 0;
    const int dt = dir ? -1 : 1;

    float xcur[8], xnxt[8];
    {
        const float* xr = xw + ((size_t)(b0 + bt) * Tt + t0) * G4;
#pragma unroll
        for (int g = 0; g < 4; g++) { xcur[g] = xr[g * 128 + jj]; xcur[4 + g] = xr[g * 128 + jj + 64]; }
    }
    __syncthreads();

    for (int s = 0; s < Tt; s++) {
        const int t = t0 + s * dt;
        if (s + 1 < Tt) {
            const float* xr = xw + ((size_t)(b0 + bt) * Tt + (t + dt)) * G4;
#pragma unroll
            for (int g = 0; g < 4; g++) { xnxt[g] = xr[g * 128 + jj]; xnxt[4 + g] = xr[g * 128 + jj + 64]; }
        }

        float acc[4][4];
#pragma unroll
        for (int nt = 0; nt < 4; nt++)
#pragma unroll
            for (int q = 0; q < 4; q++) acc[nt][q] = 0.f;

#pragma unroll
        for (int ks = 0; ks < 16; ks++) {
            const int kk = ks * 8;
            const uint32_t a0 = __float_as_uint(h_s[gid * 132 + kk + tig]);
            const uint32_t a2 = __float_as_uint(h_s[gid * 132 + kk + tig + 4]);
#pragma unroll
            for (int nt = 0; nt < 4; nt++) {
                uint32_t bf0, bf1;
                if (ks < 4) { bf0 = breg[ks][nt][0]; bf1 = breg[ks][nt][1]; }
                else {
                    float2 f2 = *(const float2*)&Wfrag[wid * 3072 + ((ks - 4) * 4 + nt) * 64 + lane * 2];
                    bf0 = __float_as_uint(f2.x); bf1 = __float_as_uint(f2.y);
                }
                mma_tf32(acc[nt], a0, 0u, a2, 0u, bf0, bf1);
            }
        }
        // store recurrent gate contributions (rows gid = real batch rows)
#pragma unroll
        for (int nt = 0; nt < 4; nt++) {
            const int n = wid * 32 + nt * 8 + 2 * tig;
            *(float2*)&gbuf[gid * 520 + n] = make_float2(acc[nt][0], acc[nt][1]);
        }
        __syncthreads();

        // gate phase
#pragma unroll
        for (int r = 0; r < 2; r++) {
            const int jr = jj + r * 64;
            const float gi = gbuf[bt * 520 + jr]       + xcur[r * 4 + 0];
            const float gf = gbuf[bt * 520 + 128 + jr] + xcur[r * 4 + 1];
            const float gg = gbuf[bt * 520 + 256 + jr] + xcur[r * 4 + 2];
            const float go = gbuf[bt * 520 + 384 + jr] + xcur[r * 4 + 3];
            float c = r ? c1 : c0;
            const float si = sigm_f(gi), sf = sigm_f(gf), so = sigm_f(go);
            c = sf * c + si * tanh_f(gg);
            const float h = so * tanh_f(c);
            if (r) c1 = c; else c0 = c;
            h_s[bt * 132 + jr] = h;
            hout[((size_t)(b0 + bt) * Tt + t) * H2 + dir * Hh + jr] = h;
        }
        __syncthreads();

#pragma unroll
        for (int g = 0; g < 8; g++) xcur[g] = xnxt[g];
    }
}

// ---------------- attention scores ----------------
__launch_bounds__(256)
__global__ void att_score(const float* __restrict__ h1, const float* __restrict__ WT,
                          const float* __restrict__ v, float* __restrict__ a) {
    __shared__ float hs[8][256];
    __shared__ float red[8][8];
    const int tid = threadIdx.x;
    const int row0 = blockIdx.x * 8;
#pragma unroll
    for (int r = 0; r < 8; r++) hs[r][tid] = h1[(size_t)(row0 + r) * H2 + tid];
    __syncthreads();

    float acc[8] = {0.f, 0.f, 0.f, 0.f, 0.f, 0.f, 0.f, 0.f};
    const float4* wr = (const float4*)(WT + tid * H2);
#pragma unroll 4
    for (int q = 0; q < 64; q++) {
        float4 w4 = __ldg(wr + q);
        const int i = q * 4;
#pragma unroll
        for (int r = 0; r < 8; r++) {
            float4 h4 = *(const float4*)&hs[r][i];
            acc[r] += w4.x * h4.x + w4.y * h4.y + w4.z * h4.z + w4.w * h4.w;
        }
    }
    const float vj = v[tid];
#pragma unroll
    for (int r = 0; r < 8; r++) {
        float x = tanhf(acc[r]) * vj;
#pragma unroll
        for (int o = 16; o > 0; o >>= 1) x += __shfl_down_sync(0xffffffffu, x, o);
        acc[r] = x;
    }
    const int lane = tid & 31, wp = tid >> 5;
    if (lane == 0) {
#pragma unroll
        for (int r = 0; r < 8; r++) red[r][wp] = acc[r];
    }
    __syncthreads();
    if (tid < 8) {
        float sv = 0.f;
#pragma unroll
        for (int w = 0; w < 8; w++) sv += red[tid][w];
        a[row0 + tid] = sv;
    }
}

// ---------------- softmax over T per batch row ----------------
__global__ void softmax_t(const float* __restrict__ a, float* __restrict__ s) {
    __shared__ float red[256];
    const int b = blockIdx.x, tid = threadIdx.x;
    float v0 = (tid < Tt) ? a[b * Tt + tid] : -1e30f;
    float v1 = (tid + 256 < Tt) ? a[b * Tt + tid + 256] : -1e30f;
    red[tid] = fmaxf(v0, v1);
    __syncthreads();
    for (int o = 128; o > 0; o >>= 1) {
        if (tid < o) red[tid] = fmaxf(red[tid], red[tid + o]);
        __syncthreads();
    }
    const float m = red[0];
    __syncthreads();
    float e0 = (tid < Tt) ? expf(v0 - m) : 0.f;
    float e1 = (tid + 256 < Tt) ? expf(v1 - m) : 0.f;
    red[tid] = e0 + e1;
    __syncthreads();
    for (int o = 128; o > 0; o >>= 1) {
        if (tid < o) red[tid] += red[tid + o];
        __syncthreads();
    }
    const float inv = 1.f / red[0];
    if (tid < Tt) s[b * Tt + tid] = e0 * inv;
    if (tid + 256 < Tt) s[b * Tt + tid + 256] = e1 * inv;
}

// ---------------- weighted[b,h] = sum_t h1[b,t,h] * s[b,t] ----------------
__global__ void weighted_sum(const float* __restrict__ h1, const float* __restrict__ s,
                             float* __restrict__ w) {
    __shared__ float ss[Tt];
    const int b = blockIdx.x, tid = threadIdx.x;
    for (int t = tid; t < Tt; t += 256) ss[t] = s[b * Tt + t];
    __syncthreads();
    float acc = 0.f;
    const float* hb = h1 + (size_t)b * Tt * H2 + tid;
    for (int t = 0; t < Tt; t++) acc += hb[(size_t)t * H2] * ss[t];
    w[b * H2 + tid] = acc;
}

// ---------------- launcher ----------------
extern "C" void kernel_launch(void* const* d_in, const int* in_sizes, int n_in,
                              void* d_out, int out_size) {
    (void)in_sizes; (void)n_in; (void)out_size;
    const float* X      = (const float*)d_in[0];
    const float* w_ih0f = (const float*)d_in[1];
    const float* w_hh0f = (const float*)d_in[2];
    const float* b_ih0f = (const float*)d_in[3];
    const float* b_hh0f = (const float*)d_in[4];
    const float* w_ih0b = (const float*)d_in[5];
    const float* w_hh0b = (const float*)d_in[6];
    const float* b_ih0b = (const float*)d_in[7];
    const float* b_hh0b = (const float*)d_in[8];
    const float* w_ih1f = (const float*)d_in[9];
    const float* w_hh1f = (const float*)d_in[10];
    const float* b_ih1f = (const float*)d_in[11];
    const float* b_hh1f = (const float*)d_in[12];
    const float* w_ih1b = (const float*)d_in[13];
    const float* w_hh1b = (const float*)d_in[14];
    const float* b_ih1b = (const float*)d_in[15];
    const float* b_hh1b = (const float*)d_in[16];
    const float* att_W  = (const float*)d_in[17];
    const float* att_v  = (const float*)d_in[18];
    const float* head_W = (const float*)d_in[19];
    const float* head_b = (const float*)d_in[20];
    float* out = (float*)d_out;

    float *Xt, *w0f, *w0b, *xw0f, *xw0b, *xw1f, *xw1b, *h0, *h1, *attWT, *aL, *sL, *ws;
    cudaGetSymbolAddress((void**)&Xt,    g_Xt);
    cudaGetSymbolAddress((void**)&w0f,   g_w0f);
    cudaGetSymbolAddress((void**)&w0b,   g_w0b);
    cudaGetSymbolAddress((void**)&xw0f,  g_xw0f);
    cudaGetSymbolAddress((void**)&xw0b,  g_xw0b);
    cudaGetSymbolAddress((void**)&xw1f,  g_xw1f);
    cudaGetSymbolAddress((void**)&xw1b,  g_xw1b);
    cudaGetSymbolAddress((void**)&h0,    g_h0);
    cudaGetSymbolAddress((void**)&h1,    g_h1);
    cudaGetSymbolAddress((void**)&attWT, g_attWT);
    cudaGetSymbolAddress((void**)&aL,    g_a);
    cudaGetSymbolAddress((void**)&sL,    g_s);
    cudaGetSymbolAddress((void**)&ws,    g_ws);

    const int gemm_smem = (3 * STG_F * 2 + 128) * 4;
    cudaFuncSetAttribute(gemm_tf32, cudaFuncAttributeMaxDynamicSharedMemorySize, gemm_smem);
    cudaFuncSetAttribute(lstm_layer_mma, cudaFuncAttributeMaxDynamicSharedMemorySize, LSTM2_SMEM_B);

    // 1. layout prep
    transpose_x<<<dim3((Tt + 31) / 32, (KP0 + 31) / 32, Bn), dim3(32, 8)>>>(X, Xt);
    pad_w<<<G4, KP0>>>(w_ih0f, w0f);
    pad_w<<<G4, KP0>>>(w_ih0b, w0b);
    transpose_att<<<H2, H2>>>(att_W, attWT);

    // 2. layer-0 input projections
    dim3 gproj(MBT / 128, G4 / 128);
    gemm_tf32<<<gproj, 256, gemm_smem>>>(Xt, w0f, b_ih0f, b_hh0f, xw0f, G4, KP0);
    gemm_tf32<<<gproj, 256, gemm_smem>>>(Xt, w0b, b_ih0b, b_hh0b, xw0b, G4, KP0);

    // 3. layer-0 recurrence (tensor-core mma)
    lstm_layer_mma<<<128, 512, LSTM2_SMEM_B>>>(xw0f, xw0b, w_hh0f, w_hh0b, h0);

    // 4. layer-1 input projections
    gemm_tf32<<<gproj, 256, gemm_smem>>>(h0, w_ih1f, b_ih1f, b_hh1f, xw1f, G4, H2);
    gemm_tf32<<<gproj, 256, gemm_smem>>>(h0, w_ih1b, b_ih1b, b_hh1b, xw1b, G4, H2);

    // 5. layer-1 recurrence
    lstm_layer_mma<<<128, 512, LSTM2_SMEM_B>>>(xw1f, xw1b, w_hh1f, w_hh1b, h1);

    // 6. attention + softmax + context
    att_score<<<MBT / 8, 256>>>(h1, attWT, att_v, aL);
    softmax_t<<<Bn, 256>>>(aL, sL);
    weighted_sum<<<Bn, 256>>>(h1, sL, ws);

    // 7. classifier head (fp32)
    gemm_bias<<<dim3((Bn + 127) / 128, (NC + 127) / 128), 256>>>(
        ws, head_W, head_b, out, Bn, NC, H2);
}

// round 7
// speedup vs baseline: 4.0833x; 1.1331x over previous
#include <cuda_runtime.h>
#include <math.h>
#include <stddef.h>
#include <stdint.h>

#define Bn 512
#define Cc 271
#define Tt 281
#define Hh 128
#define G4 512      // 4H
#define H2 256      // 2H
#define NC 1854
#define NCP 1920    // padded classes
#define MBT (Bn*Tt) // 143872 rows
#define KP0 288     // padded K for layer-0

// ---------------- scratch ----------------
__device__ float g_Xt[(size_t)MBT * KP0];
__device__ float g_w0f[G4 * KP0];
__device__ float g_w0b[G4 * KP0];
__device__ float g_xw0f[(size_t)MBT * G4];
__device__ float g_xw0b[(size_t)MBT * G4];
__device__ float g_xw1f[(size_t)MBT * G4];
__device__ float g_xw1b[(size_t)MBT * G4];
__device__ float g_h0[(size_t)MBT * H2];
__device__ float g_h1[(size_t)MBT * H2];
__device__ float g_attWT[H2 * H2];
__device__ float g_a[MBT];
__device__ float g_s[MBT];
__device__ float g_ws[Bn * H2];
__device__ float g_wHp[NCP * H2];   // padded head weights
__device__ float g_bHp[NCP];        // padded head bias
__device__ float g_outp[Bn * NCP];  // padded head output

// ---------------- X [B,C,T] -> Xt [B,T,KP0] ----------------
__global__ void transpose_x(const float* __restrict__ X, float* __restrict__ Xt) {
    __shared__ float tile[32][33];
    const int b = blockIdx.z;
    const int t0 = blockIdx.x * 32;
    const int c0 = blockIdx.y * 32;
    for (int i = threadIdx.y; i < 32; i += 8) {
        int c = c0 + i, t = t0 + threadIdx.x;
        tile[i][threadIdx.x] = (c < Cc && t < Tt) ? X[((size_t)b * Cc + c) * Tt + t] : 0.f;
    }
    __syncthreads();
    for (int i = threadIdx.y; i < 32; i += 8) {
        int t = t0 + i, c = c0 + threadIdx.x;
        if (t < Tt && c < KP0) Xt[((size_t)b * Tt + t) * KP0 + c] = tile[threadIdx.x][i];
    }
}

__global__ void pad_w(const float* __restrict__ W, float* __restrict__ Wp) {
    int r = blockIdx.x, c = threadIdx.x;
    Wp[r * KP0 + c] = (c < Cc) ? W[r * Cc + c] : 0.f;
}

__global__ void transpose_att(const float* __restrict__ W, float* __restrict__ WT) {
    int i = blockIdx.x, j = threadIdx.x;
    WT[j * H2 + i] = W[i * H2 + j];
}

__global__ void pad_head_w(const float* __restrict__ W, float* __restrict__ Wp) {
    int r = blockIdx.x, c = threadIdx.x;
    Wp[r * H2 + c] = (r < NC) ? W[r * H2 + c] : 0.f;
}
__global__ void pad_head_b(const float* __restrict__ b, float* __restrict__ bp) {
    int i = blockIdx.x * blockDim.x + threadIdx.x;
    if (i < NCP) bp[i] = (i < NC) ? b[i] : 0.f;
}
__global__ void zero_a(float* __restrict__ a) {
    int i = blockIdx.x * blockDim.x + threadIdx.x;
    if (i < MBT) a[i] = 0.f;
}
__global__ void copy_head(const float* __restrict__ outp, float* __restrict__ out) {
    int n = blockIdx.y * blockDim.x + threadIdx.x;
    if (n < NC) out[(size_t)blockIdx.x * NC + n] = outp[(size_t)blockIdx.x * NCP + n];
}

// ---------------- tf32 helpers ----------------
__device__ __forceinline__ uint32_t tf32u(float x) {
    uint32_t u;
    asm("cvt.rna.tf32.f32 %0, %1;" : "=r"(u) : "f"(x));
    return u;
}
__device__ __forceinline__ void mma_tf32(float* c, uint32_t a0, uint32_t a1, uint32_t a2,
                                         uint32_t a3, uint32_t b0, uint32_t b1) {
    asm volatile(
        "mma.sync.aligned.m16n8k8.row.col.f32.tf32.tf32.f32 "
        "{%0,%1,%2,%3}, {%4,%5,%6,%7}, {%8,%9}, {%0,%1,%2,%3};\n"
        : "+f"(c[0]), "+f"(c[1]), "+f"(c[2]), "+f"(c[3])
        : "r"(a0), "r"(a1), "r"(a2), "r"(a3), "r"(b0), "r"(b1));
}
__device__ __forceinline__ void cpa16(float* dst, const float* src) {
    unsigned s = (unsigned)__cvta_generic_to_shared(dst);
    asm volatile("cp.async.cg.shared.global [%0], [%1], 16;" :: "r"(s), "l"(src));
}

__device__ __forceinline__ float sigm_f(float x) {
    return __fdividef(1.f, 1.f + __expf(-x));
}
__device__ __forceinline__ float tanh_f(float x) {
    float a = fabsf(x);
    float e = __expf(2.f * a);
    float t = 1.f - __fdividef(2.f, e + 1.f);
    return copysignf(t, x);
}

// ---------------- TF32 GEMM, cp.async 3-stage ----------------
#define LDA 36
#define STG_F (128 * LDA)
#define GEMM_SMEM_B ((3 * STG_F * 2 + 128) * 4)

#define GEMM_LOAD_STAGE(slot, k0)                                              \
    {                                                                          \
        _Pragma("unroll")                                                      \
        for (int i = 0; i < 4; i++) {                                          \
            int r = lr + i * 32;                                               \
            cpa16(&As[(slot) * STG_F + r * LDA + lc],                          \
                  A + (size_t)(m0 + r) * K + (k0) + lc);                       \
            cpa16(&Bs[(slot) * STG_F + r * LDA + lc],                          \
                  Bw + (size_t)(n0 + r) * K + (k0) + lc);                      \
        }                                                                      \
    }

#define GEMM_MAINLOOP()                                                        \
    GEMM_LOAD_STAGE(0, 0);                                                     \
    asm volatile("cp.async.commit_group;");                                    \
    GEMM_LOAD_STAGE(1, 32);                                                    \
    asm volatile("cp.async.commit_group;");                                    \
    for (int ks = 0; ks < nStages; ks++) {                                     \
        asm volatile("cp.async.wait_group 1;");                                \
        __syncthreads();                                                       \
        const int nx = ks + 2;                                                 \
        if (nx < nStages) GEMM_LOAD_STAGE(nx % 3, nx * 32);                    \
        asm volatile("cp.async.commit_group;");                                \
        const float* Ab = As + (ks % 3) * STG_F;                               \
        const float* Bb = Bs + (ks % 3) * STG_F;                               \
        _Pragma("unroll")                                                      \
        for (int kt = 0; kt < 4; kt++) {                                       \
            const int kk = kt * 8;                                             \
            uint32_t af[4][4], bf[4][2];                                       \
            _Pragma("unroll")                                                  \
            for (int mt = 0; mt < 4; mt++) {                                   \
                const int r = warpM + mt * 16 + gid;                           \
                af[mt][0] = __float_as_uint(Ab[r * LDA + kk + tig]);           \
                af[mt][1] = __float_as_uint(Ab[(r + 8) * LDA + kk + tig]);     \
                af[mt][2] = __float_as_uint(Ab[r * LDA + kk + tig + 4]);       \
                af[mt][3] = __float_as_uint(Ab[(r + 8) * LDA + kk + tig + 4]); \
            }                                                                  \
            _Pragma("unroll")                                                  \
            for (int nt = 0; nt < 4; nt++) {                                   \
                const int r = warpN + nt * 8 + gid;                            \
                bf[nt][0] = __float_as_uint(Bb[r * LDA + kk + tig]);           \
                bf[nt][1] = __float_as_uint(Bb[r * LDA + kk + tig + 4]);       \
            }                                                                  \
            _Pragma("unroll")                                                  \
            for (int mt = 0; mt < 4; mt++)                                     \
                _Pragma("unroll")                                              \
                for (int nt = 0; nt < 4; nt++)                                 \
                    mma_tf32(c[mt][nt], af[mt][0], af[mt][1], af[mt][2],       \
                             af[mt][3], bf[nt][0], bf[nt][1]);                 \
        }                                                                      \
        __syncthreads();                                                       \
    }

__launch_bounds__(256)
__global__ void gemm_tf32(const float* __restrict__ A, const float* __restrict__ Bw,
                          const float* __restrict__ bias1, const float* __restrict__ bias2,
                          float* __restrict__ C, int N, int K) {
    extern __shared__ float sm[];
    float* As = sm;
    float* Bs = sm + 3 * STG_F;
    float* bias_s = Bs + 3 * STG_F;

    const int tid = threadIdx.x;
    const int m0 = blockIdx.x * 128, n0 = blockIdx.y * 128;
    const int wid = tid >> 5, lane = tid & 31;
    const int warpM = (wid >> 2) * 64;
    const int warpN = (wid & 3) * 32;
    const int gid = lane >> 2, tig = lane & 3;
    const int lr = tid >> 3, lc = (tid & 7) * 4;

    if (tid < 128) {
        float b = bias1[n0 + tid];
        if (bias2) b += bias2[n0 + tid];
        bias_s[tid] = b;
    }

    float c[4][4][4];
#pragma unroll
    for (int mt = 0; mt < 4; mt++)
#pragma unroll
        for (int nt = 0; nt < 4; nt++)
#pragma unroll
            for (int q = 0; q < 4; q++) c[mt][nt][q] = 0.f;

    const int nStages = K >> 5;
    GEMM_MAINLOOP();

#pragma unroll
    for (int mt = 0; mt < 4; mt++) {
        const int m = m0 + warpM + mt * 16 + gid;
#pragma unroll
        for (int nt = 0; nt < 4; nt++) {
            const int nn = warpN + nt * 8 + tig * 2;
            const float bx = bias_s[nn], by = bias_s[nn + 1];
            float2 v0 = make_float2(c[mt][nt][0] + bx, c[mt][nt][1] + by);
            float2 v1 = make_float2(c[mt][nt][2] + bx, c[mt][nt][3] + by);
            *(float2*)(C + (size_t)m * N + n0 + nn) = v0;
            *(float2*)(C + (size_t)(m + 8) * N + n0 + nn) = v1;
        }
    }
}

// ---------------- fused attention GEMM: a[m] += sum_n tanh((h1@attW)[m,n]) * v[n] ----------------
__launch_bounds__(256)
__global__ void att_gemm(const float* __restrict__ A, const float* __restrict__ Bw,
                         const float* __restrict__ v, float* __restrict__ aOut, int K) {
    extern __shared__ float sm[];
    float* As = sm;
    float* Bs = sm + 3 * STG_F;
    float* vbuf = Bs + 3 * STG_F;       // [128]
    float* red = vbuf + 128;            // [128]

    const int tid = threadIdx.x;
    const int m0 = blockIdx.x * 128, n0 = blockIdx.y * 128;
    const int wid = tid >> 5, lane = tid & 31;
    const int warpM = (wid >> 2) * 64;
    const int warpN = (wid & 3) * 32;
    const int gid = lane >> 2, tig = lane & 3;
    const int lr = tid >> 3, lc = (tid & 7) * 4;

    if (tid < 128) { vbuf[tid] = v[n0 + tid]; red[tid] = 0.f; }

    float c[4][4][4];
#pragma unroll
    for (int mt = 0; mt < 4; mt++)
#pragma unroll
        for (int nt = 0; nt < 4; nt++)
#pragma unroll
            for (int q = 0; q < 4; q++) c[mt][nt][q] = 0.f;

    const int nStages = K >> 5;
    GEMM_MAINLOOP();

    // epilogue: tanh * v, reduce over n
    float part[8];
#pragma unroll
    for (int i = 0; i < 8; i++) part[i] = 0.f;
#pragma unroll
    for (int mt = 0; mt < 4; mt++)
#pragma unroll
        for (int nt = 0; nt < 4; nt++) {
            const int nl = warpN + nt * 8 + tig * 2;
            const float vv0 = vbuf[nl], vv1 = vbuf[nl + 1];
            part[2 * mt]     += tanh_f(c[mt][nt][0]) * vv0 + tanh_f(c[mt][nt][1]) * vv1;
            part[2 * mt + 1] += tanh_f(c[mt][nt][2]) * vv0 + tanh_f(c[mt][nt][3]) * vv1;
        }
#pragma unroll
    for (int i = 0; i < 8; i++) {
        part[i] += __shfl_xor_sync(0xffffffffu, part[i], 1);
        part[i] += __shfl_xor_sync(0xffffffffu, part[i], 2);
    }
    if (tig == 0) {
#pragma unroll
        for (int i = 0; i < 8; i++) {
            const int row = warpM + (i >> 1) * 16 + (i & 1) * 8 + gid;
            atomicAdd(&red[row], part[i]);
        }
    }
    __syncthreads();
    if (tid < 128) atomicAdd(&aOut[m0 + tid], red[tid]);
}

// ---------------- bidirectional LSTM: M=16 real batches, tensor-core recurrence ----------------
// 64 CTAs (32 batch-tiles x 2 dirs), 256 threads = 8 warps, each warp N=64 gate cols.
// W_hh fragments: ks 0..7 in registers, ks 8..15 in smem. xw staged via cp.async.
#define L_WF 32768                   // 8 warps * 8ks * 8nt * 64
#define L_HS (16 * 132)              // 2112
#define L_GB (16 * 516)              // 8256
#define L_XB (16 * 512)              // 8192
#define LSTM3_SMEM_B ((L_WF + L_HS + L_GB + L_XB) * 4)   // 205312 B
__launch_bounds__(256)
__global__ void lstm_mma2(const float* __restrict__ xwf, const float* __restrict__ xwb,
                          const float* __restrict__ whf, const float* __restrict__ whb,
                          float* __restrict__ hout) {
    extern __shared__ float smf[];
    float* Wfrag = smf;                 // [8 warps][8 ks][8 nt][64]
    float* h_s   = smf + L_WF;          // [16][132]
    float* gbuf  = h_s + L_HS;          // [16][516]
    float* xbuf  = gbuf + L_GB;         // [16][512]

    const int tid = threadIdx.x;
    const int wid = tid >> 5, lane = tid & 31;
    const int gid = lane >> 2, tig = lane & 3;
    const int dir = blockIdx.x >> 5;
    const int b0  = (blockIdx.x & 31) * 16;
    const float* W  = dir ? whb : whf;
    const float* xw = dir ? xwb : xwf;

    // prepack: ks 0..7 -> registers
    uint32_t breg[8][8][2];
#pragma unroll
    for (int ks = 0; ks < 8; ks++)
#pragma unroll
        for (int nt = 0; nt < 8; nt++) {
            const int n = wid * 64 + nt * 8 + gid;
            const int k = ks * 8 + tig;
            breg[ks][nt][0] = tf32u(W[n * Hh + k]);
            breg[ks][nt][1] = tf32u(W[n * Hh + k + 4]);
        }
    // ks 8..15 -> smem
    for (int ks = 8; ks < 16; ks++)
#pragma unroll
        for (int nt = 0; nt < 8; nt++) {
            const int n = wid * 64 + nt * 8 + gid;
            const int k = ks * 8 + tig;
            float2 f2;
            f2.x = __uint_as_float(tf32u(W[n * Hh + k]));
            f2.y = __uint_as_float(tf32u(W[n * Hh + k + 4]));
            *(float2*)&Wfrag[wid * 4096 + ((ks - 8) * 8 + nt) * 64 + lane * 2] = f2;
        }
    for (int i = tid; i < L_HS; i += 256) h_s[i] = 0.f;

    // gate-phase identity: bt batch row, units u0 + 16k
    const int bt = tid >> 4;
    const int u0 = tid & 15;
    float creg[8];
#pragma unroll
    for (int k = 0; k < 8; k++) creg[k] = 0.f;

    const int t0 = dir ? (Tt - 1) : 0;
    const int dt = dir ? -1 : 1;

    // cp.async addressing (thread loads 128B of this step's xw tile)
    const float* xsrc_base = xw + ((size_t)(b0 + bt) * Tt) * G4 + u0 * 32;
    float* xdst = xbuf + bt * 512 + u0 * 32;

    __syncthreads();

    for (int s = 0; s < Tt; s++) {
        const int t = t0 + s * dt;
        // stage xw[t] for this step's gate phase (hidden under mma)
        {
            const float* src = xsrc_base + (size_t)t * G4;
#pragma unroll
            for (int q = 0; q < 8; q++) cpa16(xdst + q * 4, src + q * 4);
            asm volatile("cp.async.commit_group;");
        }

        float acc[8][4];
#pragma unroll
        for (int nt = 0; nt < 8; nt++)
#pragma unroll
            for (int q = 0; q < 4; q++) acc[nt][q] = 0.f;

#pragma unroll
        for (int ks = 0; ks < 16; ks++) {
            const int kk = ks * 8;
            const uint32_t a0 = __float_as_uint(h_s[gid * 132 + kk + tig]);
            const uint32_t a1 = __float_as_uint(h_s[(gid + 8) * 132 + kk + tig]);
            const uint32_t a2 = __float_as_uint(h_s[gid * 132 + kk + tig + 4]);
            const uint32_t a3 = __float_as_uint(h_s[(gid + 8) * 132 + kk + tig + 4]);
#pragma unroll
            for (int nt = 0; nt < 8; nt++) {
                uint32_t bf0, bf1;
                if (ks < 8) { bf0 = breg[ks][nt][0]; bf1 = breg[ks][nt][1]; }
                else {
                    float2 f2 = *(const float2*)&Wfrag[wid * 4096 + ((ks - 8) * 8 + nt) * 64 + lane * 2];
                    bf0 = __float_as_uint(f2.x); bf1 = __float_as_uint(f2.y);
                }
                mma_tf32(acc[nt], a0, a1, a2, a3, bf0, bf1);
            }
        }
#pragma unroll
        for (int nt = 0; nt < 8; nt++) {
            const int n = wid * 64 + nt * 8 + 2 * tig;
            *(float2*)&gbuf[gid * 516 + n] = make_float2(acc[nt][0], acc[nt][1]);
            *(float2*)&gbuf[(gid + 8) * 516 + n] = make_float2(acc[nt][2], acc[nt][3]);
        }
        asm volatile("cp.async.wait_group 0;");
        __syncthreads();

        // gate phase: 8 units per thread
#pragma unroll
        for (int k = 0; k < 8; k++) {
            const int u = u0 + 16 * k;
            const float gi = gbuf[bt * 516 + u]       + xbuf[bt * 512 + u];
            const float gf = gbuf[bt * 516 + 128 + u] + xbuf[bt * 512 + 128 + u];
            const float gg = gbuf[bt * 516 + 256 + u] + xbuf[bt * 512 + 256 + u];
            const float go = gbuf[bt * 516 + 384 + u] + xbuf[bt * 512 + 384 + u];
            const float si = sigm_f(gi), sf = sigm_f(gf), so = sigm_f(go);
            float c = sf * creg[k] + si * tanh_f(gg);
            creg[k] = c;
            const float h = so * tanh_f(c);
            h_s[bt * 132 + u] = h;
            hout[((size_t)(b0 + bt) * Tt + t) * H2 + dir * Hh + u] = h;
        }
        __syncthreads();
    }
}

// ---------------- softmax over T ----------------
__global__ void softmax_t(const float* __restrict__ a, float* __restrict__ s) {
    __shared__ float red[256];
    const int b = blockIdx.x, tid = threadIdx.x;
    float v0 = (tid < Tt) ? a[b * Tt + tid] : -1e30f;
    float v1 = (tid + 256 < Tt) ? a[b * Tt + tid + 256] : -1e30f;
    red[tid] = fmaxf(v0, v1);
    __syncthreads();
    for (int o = 128; o > 0; o >>= 1) {
        if (tid < o) red[tid] = fmaxf(red[tid], red[tid + o]);
        __syncthreads();
    }
    const float m = red[0];
    __syncthreads();
    float e0 = (tid < Tt) ? expf(v0 - m) : 0.f;
    float e1 = (tid + 256 < Tt) ? expf(v1 - m) : 0.f;
    red[tid] = e0 + e1;
    __syncthreads();
    for (int o = 128; o > 0; o >>= 1) {
        if (tid < o) red[tid] += red[tid + o];
        __syncthreads();
    }
    const float inv = 1.f / red[0];
    if (tid < Tt) s[b * Tt + tid] = e0 * inv;
    if (tid + 256 < Tt) s[b * Tt + tid + 256] = e1 * inv;
}

// ---------------- weighted[b,h] = sum_t h1[b,t,h] * s[b,t] ----------------
__global__ void weighted_sum(const float* __restrict__ h1, const float* __restrict__ s,
                             float* __restrict__ w) {
    __shared__ float ss[Tt];
    const int b = blockIdx.x, tid = threadIdx.x;
    for (int t = tid; t < Tt; t += 256) ss[t] = s[b * Tt + t];
    __syncthreads();
    float acc = 0.f;
    const float* hb = h1 + (size_t)b * Tt * H2 + tid;
    for (int t = 0; t < Tt; t++) acc += hb[(size_t)t * H2] * ss[t];
    w[b * H2 + tid] = acc;
}

// ---------------- launcher ----------------
extern "C" void kernel_launch(void* const* d_in, const int* in_sizes, int n_in,
                              void* d_out, int out_size) {
    (void)in_sizes; (void)n_in; (void)out_size;
    const float* X      = (const float*)d_in[0];
    const float* w_ih0f = (const float*)d_in[1];
    const float* w_hh0f = (const float*)d_in[2];
    const float* b_ih0f = (const float*)d_in[3];
    const float* b_hh0f = (const float*)d_in[4];
    const float* w_ih0b = (const float*)d_in[5];
    const float* w_hh0b = (const float*)d_in[6];
    const float* b_ih0b = (const float*)d_in[7];
    const float* b_hh0b = (const float*)d_in[8];
    const float* w_ih1f = (const float*)d_in[9];
    const float* w_hh1f = (const float*)d_in[10];
    const float* b_ih1f = (const float*)d_in[11];
    const float* b_hh1f = (const float*)d_in[12];
    const float* w_ih1b = (const float*)d_in[13];
    const float* w_hh1b = (const float*)d_in[14];
    const float* b_ih1b = (const float*)d_in[15];
    const float* b_hh1b = (const float*)d_in[16];
    const float* att_W  = (const float*)d_in[17];
    const float* att_v  = (const float*)d_in[18];
    const float* head_W = (const float*)d_in[19];
    const float* head_b = (const float*)d_in[20];
    float* out = (float*)d_out;

    float *Xt, *w0f, *w0b, *xw0f, *xw0b, *xw1f, *xw1b, *h0, *h1, *attWT, *aL, *sL, *ws;
    float *wHp, *bHp, *outp;
    cudaGetSymbolAddress((void**)&Xt,    g_Xt);
    cudaGetSymbolAddress((void**)&w0f,   g_w0f);
    cudaGetSymbolAddress((void**)&w0b,   g_w0b);
    cudaGetSymbolAddress((void**)&xw0f,  g_xw0f);
    cudaGetSymbolAddress((void**)&xw0b,  g_xw0b);
    cudaGetSymbolAddress((void**)&xw1f,  g_xw1f);
    cudaGetSymbolAddress((void**)&xw1b,  g_xw1b);
    cudaGetSymbolAddress((void**)&h0,    g_h0);
    cudaGetSymbolAddress((void**)&h1,    g_h1);
    cudaGetSymbolAddress((void**)&attWT, g_attWT);
    cudaGetSymbolAddress((void**)&aL,    g_a);
    cudaGetSymbolAddress((void**)&sL,    g_s);
    cudaGetSymbolAddress((void**)&ws,    g_ws);
    cudaGetSymbolAddress((void**)&wHp,   g_wHp);
    cudaGetSymbolAddress((void**)&bHp,   g_bHp);
    cudaGetSymbolAddress((void**)&outp,  g_outp);

    cudaFuncSetAttribute(gemm_tf32, cudaFuncAttributeMaxDynamicSharedMemorySize, GEMM_SMEM_B);
    cudaFuncSetAttribute(att_gemm, cudaFuncAttributeMaxDynamicSharedMemorySize, GEMM_SMEM_B + 512);
    cudaFuncSetAttribute(lstm_mma2, cudaFuncAttributeMaxDynamicSharedMemorySize, LSTM3_SMEM_B);

    // 1. layout prep
    transpose_x<<<dim3((Tt + 31) / 32, (KP0 + 31) / 32, Bn), dim3(32, 8)>>>(X, Xt);
    pad_w<<<G4, KP0>>>(w_ih0f, w0f);
    pad_w<<<G4, KP0>>>(w_ih0b, w0b);
    transpose_att<<<H2, H2>>>(att_W, attWT);
    pad_head_w<<<NCP, H2>>>(head_W, wHp);
    pad_head_b<<<(NCP + 127) / 128, 128>>>(head_b, bHp);
    zero_a<<<(MBT + 1023) / 1024, 1024>>>(aL);

    // 2. layer-0 input projections
    dim3 gproj(MBT / 128, G4 / 128);
    gemm_tf32<<<gproj, 256, GEMM_SMEM_B>>>(Xt, w0f, b_ih0f, b_hh0f, xw0f, G4, KP0);
    gemm_tf32<<<gproj, 256, GEMM_SMEM_B>>>(Xt, w0b, b_ih0b, b_hh0b, xw0b, G4, KP0);

    // 3. layer-0 recurrence
    lstm_mma2<<<64, 256, LSTM3_SMEM_B>>>(xw0f, xw0b, w_hh0f, w_hh0b, h0);

    // 4. layer-1 input projections
    gemm_tf32<<<gproj, 256, GEMM_SMEM_B>>>(h0, w_ih1f, b_ih1f, b_hh1f, xw1f, G4, H2);
    gemm_tf32<<<gproj, 256, GEMM_SMEM_B>>>(h0, w_ih1b, b_ih1b, b_hh1b, xw1b, G4, H2);

    // 5. layer-1 recurrence
    lstm_mma2<<<64, 256, LSTM3_SMEM_B>>>(xw1f, xw1b, w_hh1f, w_hh1b, h1);

    // 6. attention (fused tf32 GEMM) + softmax + context
    att_gemm<<<dim3(MBT / 128, H2 / 128), 256, GEMM_SMEM_B + 512>>>(h1, attWT, att_v, aL, H2);
    softmax_t<<<Bn, 256>>>(aL, sL);
    weighted_sum<<<Bn, 256>>>(h1, sL, ws);

    // 7. classifier head (tf32, padded) + copy
    gemm_tf32<<<dim3(Bn / 128, NCP / 128), 256, GEMM_SMEM_B>>>(ws, wHp, bHp, nullptr, outp, NCP, H2);
    copy_head<<<dim3(Bn, (NC + 255) / 256), 256>>>(outp, out);
}